// round 1
// baseline (speedup 1.0000x reference)
#include <cuda_runtime.h>
#include <cuda_bf16.h>
#include <math.h>

// ----------------------------------------------------------------------------
// Transformer block, fp32 baseline.
//   B=2, N=2048, C=1024, H=16, D=64, FF=4096.  M = B*N = 4096 rows.
// Pipeline:
//   LN1 -> GEMM(qkv) -> flash-attn -> GEMM(proj)+res -> LN2
//       -> GEMM(fc1)+gelu -> GEMM(fc2)+res -> out
// ----------------------------------------------------------------------------

#define M_ROWS 4096
#define CDIM   1024
#define FFDIM  4096
#define NSEQ   2048
#define NHEAD  16
#define HDIM   64

// Scratch (device globals; no allocation allowed).
__device__ float g_h  [M_ROWS * CDIM];    // LN1 output
__device__ float g_qkv[M_ROWS * 3 * CDIM];
__device__ float g_o  [M_ROWS * CDIM];    // attention output
__device__ float g_x1 [M_ROWS * CDIM];    // post-attn residual
__device__ float g_h2 [M_ROWS * CDIM];    // LN2 output
__device__ float g_ff [M_ROWS * FFDIM];   // gelu(fc1)

// ----------------------------------------------------------------------------
// LayerNorm: one block per row of 1024, 256 threads, float4.
// ----------------------------------------------------------------------------
__global__ void ln_kernel(const float* __restrict__ x,
                          const float* __restrict__ g,
                          const float* __restrict__ b,
                          float* __restrict__ y) {
    int row = blockIdx.x;
    int t = threadIdx.x;                      // 0..255
    const float4* xr = (const float4*)(x + (size_t)row * CDIM);
    float4 v = xr[t];
    float s  = v.x + v.y + v.z + v.w;
    float ss = v.x*v.x + v.y*v.y + v.z*v.z + v.w*v.w;

    // warp reduce
    #pragma unroll
    for (int off = 16; off > 0; off >>= 1) {
        s  += __shfl_xor_sync(0xffffffffu, s,  off);
        ss += __shfl_xor_sync(0xffffffffu, ss, off);
    }
    __shared__ float sbuf[8], ssbuf[8];
    int warp = t >> 5, lane = t & 31;
    if (lane == 0) { sbuf[warp] = s; ssbuf[warp] = ss; }
    __syncthreads();
    float tot = 0.f, tot2 = 0.f;
    #pragma unroll
    for (int w = 0; w < 8; ++w) { tot += sbuf[w]; tot2 += ssbuf[w]; }

    float mean = tot * (1.0f / CDIM);
    float var  = tot2 * (1.0f / CDIM) - mean * mean;
    float rstd = rsqrtf(var + 1e-5f);

    float4 gg = ((const float4*)g)[t];
    float4 bb = ((const float4*)b)[t];
    float4 o;
    o.x = (v.x - mean) * rstd * gg.x + bb.x;
    o.y = (v.y - mean) * rstd * gg.y + bb.y;
    o.z = (v.z - mean) * rstd * gg.z + bb.z;
    o.w = (v.w - mean) * rstd * gg.w + bb.w;
    ((float4*)(y + (size_t)row * CDIM))[t] = o;
}

// ----------------------------------------------------------------------------
// SGEMM: C[M,N] = A[M,K] @ B[K,N]  (+bias, +residual, gelu per MODE)
// BM=BN=128, BK=16. 256 threads (16x16), 8x8 per thread.
// MODE 0: plain   MODE 1: res + AB + bias   MODE 2: gelu(AB + bias)
// ----------------------------------------------------------------------------
__device__ __forceinline__ float gelu_exact(float v) {
    return 0.5f * v * (1.0f + erff(v * 0.70710678118654752f));
}

template <int MODE>
__global__ void __launch_bounds__(256)
sgemm_kernel(const float* __restrict__ A, const float* __restrict__ B,
             const float* __restrict__ bias, const float* __restrict__ res,
             float* __restrict__ C, int M, int N, int K) {
    __shared__ float As[16][136];   // transposed: As[k][m]
    __shared__ float Bs[16][132];   // Bs[k][n]

    const int t  = threadIdx.x;
    const int tx = t & 15;          // 0..15 -> N
    const int ty = t >> 4;          // 0..15 -> M
    const int row0 = blockIdx.y * 128;
    const int col0 = blockIdx.x * 128;

    float c[8][8];
    #pragma unroll
    for (int i = 0; i < 8; ++i)
        #pragma unroll
        for (int j = 0; j < 8; ++j) c[i][j] = 0.f;

    for (int k0 = 0; k0 < K; k0 += 16) {
        // load A tile (128x16) transposed, 2 float4 per thread
        #pragma unroll
        for (int p = 0; p < 2; ++p) {
            int f    = p * 256 + t;          // 0..511
            int arow = f >> 2;               // 0..127
            int ac   = (f & 3) << 2;         // 0,4,8,12
            float4 av = *(const float4*)&A[(size_t)(row0 + arow) * K + k0 + ac];
            As[ac + 0][arow] = av.x;
            As[ac + 1][arow] = av.y;
            As[ac + 2][arow] = av.z;
            As[ac + 3][arow] = av.w;
        }
        // load B tile (16x128), 2 float4 per thread
        #pragma unroll
        for (int p = 0; p < 2; ++p) {
            int f    = p * 256 + t;
            int brow = f >> 5;               // 0..15
            int bc   = (f & 31) << 2;        // 0..124
            float4 bv = *(const float4*)&B[(size_t)(k0 + brow) * N + col0 + bc];
            *(float4*)&Bs[brow][bc] = bv;
        }
        __syncthreads();

        #pragma unroll
        for (int k = 0; k < 16; ++k) {
            float a[8], bb[8];
            *(float4*)&a[0]  = *(const float4*)&As[k][ty * 8];
            *(float4*)&a[4]  = *(const float4*)&As[k][ty * 8 + 4];
            *(float4*)&bb[0] = *(const float4*)&Bs[k][tx * 8];
            *(float4*)&bb[4] = *(const float4*)&Bs[k][tx * 8 + 4];
            #pragma unroll
            for (int i = 0; i < 8; ++i)
                #pragma unroll
                for (int j = 0; j < 8; ++j)
                    c[i][j] += a[i] * bb[j];
        }
        __syncthreads();
    }

    // epilogue
    #pragma unroll
    for (int i = 0; i < 8; ++i) {
        int row = row0 + ty * 8 + i;
        #pragma unroll
        for (int j4 = 0; j4 < 2; ++j4) {
            int col = col0 + tx * 8 + j4 * 4;
            float4 v;
            v.x = c[i][j4 * 4 + 0];
            v.y = c[i][j4 * 4 + 1];
            v.z = c[i][j4 * 4 + 2];
            v.w = c[i][j4 * 4 + 3];
            if (MODE >= 1) {
                float4 bv = *(const float4*)&bias[col];
                v.x += bv.x; v.y += bv.y; v.z += bv.z; v.w += bv.w;
            }
            if (MODE == 1) {
                float4 rv = *(const float4*)&res[(size_t)row * N + col];
                v.x += rv.x; v.y += rv.y; v.z += rv.z; v.w += rv.w;
            }
            if (MODE == 2) {
                v.x = gelu_exact(v.x); v.y = gelu_exact(v.y);
                v.z = gelu_exact(v.z); v.w = gelu_exact(v.w);
            }
            *(float4*)&C[(size_t)row * N + col] = v;
        }
    }
}

// ----------------------------------------------------------------------------
// Flash attention: grid (NSEQ/128, B*H), 128 threads, 1 thread = 1 q-row.
// q (pre-scaled) and o accumulator in registers; KV tiles of 8 rows in smem,
// broadcast-read (conflict-free). Online softmax per thread.
// ----------------------------------------------------------------------------
#define TKV 8

__global__ void __launch_bounds__(128)
attn_kernel(const float* __restrict__ qkv, float* __restrict__ o_out) {
    __shared__ float ks[TKV][68];
    __shared__ float vs[TKV][68];

    const int t  = threadIdx.x;
    const int bh = blockIdx.y;
    const int b  = bh >> 4;
    const int h  = bh & 15;
    const int r  = blockIdx.x * 128 + t;

    const float* qrow = qkv + ((size_t)(b * NSEQ + r)) * (3 * CDIM) + h * HDIM;
    float q[64];
    #pragma unroll
    for (int i = 0; i < 16; ++i) {
        float4 v = *(const float4*)&qrow[i * 4];
        q[i*4+0] = v.x * 0.125f;   // fold scale = D^-0.5 into q
        q[i*4+1] = v.y * 0.125f;
        q[i*4+2] = v.z * 0.125f;
        q[i*4+3] = v.w * 0.125f;
    }
    float o[64];
    #pragma unroll
    for (int i = 0; i < 64; ++i) o[i] = 0.f;
    float mx = -1e30f, l = 0.f;

    const float* kbase = qkv + ((size_t)b * NSEQ) * (3 * CDIM) + CDIM     + h * HDIM;
    const float* vbase = qkv + ((size_t)b * NSEQ) * (3 * CDIM) + 2 * CDIM + h * HDIM;

    const int jj = t >> 4;            // 0..7 : kv row within tile
    const int c4 = (t & 15) << 2;     // 0..60 : col

    for (int t0 = 0; t0 < NSEQ; t0 += TKV) {
        __syncthreads();
        *(float4*)&ks[jj][c4] = *(const float4*)&kbase[(size_t)(t0 + jj) * (3 * CDIM) + c4];
        *(float4*)&vs[jj][c4] = *(const float4*)&vbase[(size_t)(t0 + jj) * (3 * CDIM) + c4];
        __syncthreads();

        float s[TKV];
        #pragma unroll
        for (int j = 0; j < TKV; ++j) {
            float a0 = 0.f, a1 = 0.f, a2 = 0.f, a3 = 0.f;
            #pragma unroll
            for (int d = 0; d < 64; d += 4) {
                float4 kk = *(const float4*)&ks[j][d];
                a0 += q[d + 0] * kk.x;
                a1 += q[d + 1] * kk.y;
                a2 += q[d + 2] * kk.z;
                a3 += q[d + 3] * kk.w;
            }
            s[j] = (a0 + a1) + (a2 + a3);
        }

        float tmax = s[0];
        #pragma unroll
        for (int j = 1; j < TKV; ++j) tmax = fmaxf(tmax, s[j]);
        float m_new = fmaxf(mx, tmax);
        float corr  = __expf(mx - m_new);
        mx = m_new;
        l *= corr;
        #pragma unroll
        for (int d = 0; d < 64; ++d) o[d] *= corr;

        #pragma unroll
        for (int j = 0; j < TKV; ++j) {
            float p = __expf(s[j] - m_new);
            l += p;
            #pragma unroll
            for (int d = 0; d < 64; d += 4) {
                float4 vv = *(const float4*)&vs[j][d];
                o[d + 0] += p * vv.x;
                o[d + 1] += p * vv.y;
                o[d + 2] += p * vv.z;
                o[d + 3] += p * vv.w;
            }
        }
    }

    float inv = 1.0f / l;
    float* orow = o_out + (size_t)(b * NSEQ + r) * CDIM + h * HDIM;
    #pragma unroll
    for (int i = 0; i < 16; ++i) {
        float4 v;
        v.x = o[i*4+0] * inv;
        v.y = o[i*4+1] * inv;
        v.z = o[i*4+2] * inv;
        v.w = o[i*4+3] * inv;
        *(float4*)&orow[i * 4] = v;
    }
}

// ----------------------------------------------------------------------------
// Host launch
// ----------------------------------------------------------------------------
extern "C" void kernel_launch(void* const* d_in, const int* in_sizes, int n_in,
                              void* d_out, int out_size) {
    const float* x      = (const float*)d_in[0];
    const float* ln1_g  = (const float*)d_in[1];
    const float* ln1_b  = (const float*)d_in[2];
    const float* w_qkv  = (const float*)d_in[3];
    const float* w_proj = (const float*)d_in[4];
    const float* b_proj = (const float*)d_in[5];
    const float* ln2_g  = (const float*)d_in[6];
    const float* ln2_b  = (const float*)d_in[7];
    const float* w_fc1  = (const float*)d_in[8];
    const float* b_fc1  = (const float*)d_in[9];
    const float* w_fc2  = (const float*)d_in[10];
    const float* b_fc2  = (const float*)d_in[11];
    float* out = (float*)d_out;

    float *h, *qkv, *o, *x1, *h2, *ff;
    cudaGetSymbolAddress((void**)&h,   g_h);
    cudaGetSymbolAddress((void**)&qkv, g_qkv);
    cudaGetSymbolAddress((void**)&o,   g_o);
    cudaGetSymbolAddress((void**)&x1,  g_x1);
    cudaGetSymbolAddress((void**)&h2,  g_h2);
    cudaGetSymbolAddress((void**)&ff,  g_ff);

    // 1. LN1
    ln_kernel<<<M_ROWS, 256>>>(x, ln1_g, ln1_b, h);
    // 2. qkv = h @ w_qkv        [4096,1024]@[1024,3072]
    sgemm_kernel<0><<<dim3(3 * CDIM / 128, M_ROWS / 128), 256>>>(
        h, w_qkv, nullptr, nullptr, qkv, M_ROWS, 3 * CDIM, CDIM);
    // 3. attention
    attn_kernel<<<dim3(NSEQ / 128, 2 * NHEAD), 128>>>(qkv, o);
    // 4. x1 = x + o @ w_proj + b_proj
    sgemm_kernel<1><<<dim3(CDIM / 128, M_ROWS / 128), 256>>>(
        o, w_proj, b_proj, x, x1, M_ROWS, CDIM, CDIM);
    // 5. LN2
    ln_kernel<<<M_ROWS, 256>>>(x1, ln2_g, ln2_b, h2);
    // 6. ff = gelu(h2 @ w_fc1 + b_fc1)   [4096,1024]@[1024,4096]
    sgemm_kernel<2><<<dim3(FFDIM / 128, M_ROWS / 128), 256>>>(
        h2, w_fc1, b_fc1, nullptr, ff, M_ROWS, FFDIM, CDIM);
    // 7. out = x1 + ff @ w_fc2 + b_fc2   [4096,4096]@[4096,1024]
    sgemm_kernel<1><<<dim3(CDIM / 128, M_ROWS / 128), 256>>>(
        ff, w_fc2, b_fc2, x1, out, M_ROWS, CDIM, FFDIM);
}

// round 3
// speedup vs baseline: 1.8110x; 1.8110x over previous
#include <cuda_runtime.h>
#include <math.h>
#include <stdint.h>

#define M_ROWS 4096
#define CDIM   1024
#define FFDIM  4096
#define NSEQ   2048
#define NHEAD  16
#define HDIM   64

// ---------------- scratch (device globals; no allocs allowed) ----------------
__device__ float g_h  [M_ROWS * CDIM];
__device__ float g_qkv[M_ROWS * 3 * CDIM];
__device__ float g_o  [M_ROWS * CDIM];
__device__ float g_x1 [M_ROWS * CDIM];
__device__ float g_h2 [M_ROWS * CDIM];
__device__ float g_ff [M_ROWS * FFDIM];
__device__ float g_wqkvT[3 * CDIM * CDIM];
__device__ float g_wprojT[CDIM * CDIM];
__device__ float g_wfc1T[FFDIM * CDIM];
__device__ float g_wfc2T[CDIM * FFDIM];

// ---------------- helpers ----------------
__device__ __forceinline__ uint32_t smem_u32(const void* p) {
    uint32_t a;
    asm("{ .reg .u64 t; cvta.to.shared.u64 t, %1; cvt.u32.u64 %0, t; }" : "=r"(a) : "l"(p));
    return a;
}
__device__ __forceinline__ void cp16(uint32_t s, const void* g) {
    asm volatile("cp.async.cg.shared.global [%0], [%1], 16;" :: "r"(s), "l"(g) : "memory");
}
__device__ __forceinline__ float to_tf32(float v) {
    uint32_t u;
    asm("cvt.rna.tf32.f32 %0, %1;" : "=r"(u) : "f"(v));
    return __uint_as_float(u);
}
__device__ __forceinline__ void mma1688(float* d, const uint32_t* a, const uint32_t* b) {
    asm volatile(
        "mma.sync.aligned.m16n8k8.row.col.f32.tf32.tf32.f32 "
        "{%0,%1,%2,%3}, {%4,%5,%6,%7}, {%8,%9}, {%0,%1,%2,%3};"
        : "+f"(d[0]), "+f"(d[1]), "+f"(d[2]), "+f"(d[3])
        : "r"(a[0]), "r"(a[1]), "r"(a[2]), "r"(a[3]), "r"(b[0]), "r"(b[1]));
}
__device__ __forceinline__ float gelu_exact(float v) {
    return 0.5f * v * (1.0f + erff(v * 0.70710678118654752f));
}

// ---------------- weight transpose + tf32 round: in[K,N] -> out[N,K] --------
__global__ void transpose_k(const float* __restrict__ in, float* __restrict__ out,
                            int K, int N) {
    __shared__ float tile[32][33];
    int tx = threadIdx.x, ty = threadIdx.y;
    int x = blockIdx.x * 32 + tx;
    int y0 = blockIdx.y * 32;
    #pragma unroll
    for (int j = 0; j < 32; j += 8)
        tile[ty + j][tx] = in[(size_t)(y0 + ty + j) * N + x];
    __syncthreads();
    int ox = y0 + tx;
    int oy0 = blockIdx.x * 32;
    #pragma unroll
    for (int j = 0; j < 32; j += 8)
        out[(size_t)(oy0 + ty + j) * K + ox] = to_tf32(tile[tx][ty + j]);
}

// ---------------- mma.sync tf32 GEMM ----------------
// C[4096, N] = A[4096, K] @ BT[N, K]^T
// CTA 128x128, 8 warps (2 x 4), warp tile 64x32, k-chunk 16, 3-stage cp.async.
// MODE 0: plain   MODE 1: +bias +res   MODE 2: tf32(gelu(+bias))
#define PAD 20
#define STAGE_FLOATS 5120        // A 128*20 + B 128*20
#define GEMM_SMEM (3 * STAGE_FLOATS * 4)

template <int MODE>
__global__ void __launch_bounds__(256)
gemm_mma(const float* __restrict__ A, const float* __restrict__ BT,
         const float* __restrict__ bias, const float* __restrict__ res,
         float* __restrict__ C, int N, int K) {
    extern __shared__ float sm[];
    const int t = threadIdx.x;
    const int lane = t & 31;
    const int wid = t >> 5;
    const int wm = wid >> 2;          // 0..1
    const int wn = wid & 3;           // 0..3
    const int lr = lane >> 2;         // 0..7
    const int lc = lane & 3;          // 0..3
    const int row0 = blockIdx.y * 128, col0 = blockIdx.x * 128;
    const float* gA = A + (size_t)row0 * K;
    const float* gB = BT + (size_t)col0 * K;
    const int NC = K >> 4;

    float d[4][4][4];
    #pragma unroll
    for (int i = 0; i < 4; ++i)
        #pragma unroll
        for (int j = 0; j < 4; ++j)
            #pragma unroll
            for (int e = 0; e < 4; ++e) d[i][j][e] = 0.f;

    // prologue: 3 stages
    #pragma unroll
    for (int s = 0; s < 3; ++s) {
        float* dA = sm + s * STAGE_FLOATS;
        float* dB = dA + 2560;
        int k0 = s << 4;
        #pragma unroll
        for (int i = 0; i < 2; ++i) {
            int u = i * 256 + t;         // 0..511
            int r = u >> 2, c4 = u & 3;
            cp16(smem_u32(dA + r * PAD + c4 * 4), gA + (size_t)r * K + k0 + c4 * 4);
            cp16(smem_u32(dB + r * PAD + c4 * 4), gB + (size_t)r * K + k0 + c4 * 4);
        }
        asm volatile("cp.async.commit_group;" ::: "memory");
    }

    for (int c = 0; c < NC; ++c) {
        int b = c % 3;
        asm volatile("cp.async.wait_group 2;" ::: "memory");
        __syncthreads();

        const float* As = sm + b * STAGE_FLOATS;
        const float* Bs = As + 2560;
        #pragma unroll
        for (int s = 0; s < 2; ++s) {
            uint32_t af[4][4], bf[4][2];
            #pragma unroll
            for (int mi = 0; mi < 4; ++mi) {
                const float* p = As + (wm * 64 + mi * 16 + lr) * PAD + s * 8 + lc;
                af[mi][0] = __float_as_uint(p[0]);
                af[mi][1] = __float_as_uint(p[8 * PAD]);
                af[mi][2] = __float_as_uint(p[4]);
                af[mi][3] = __float_as_uint(p[8 * PAD + 4]);
            }
            #pragma unroll
            for (int nj = 0; nj < 4; ++nj) {
                const float* q = Bs + (wn * 32 + nj * 8 + lr) * PAD + s * 8 + lc;
                bf[nj][0] = __float_as_uint(q[0]);
                bf[nj][1] = __float_as_uint(q[4]);
            }
            #pragma unroll
            for (int mi = 0; mi < 4; ++mi)
                #pragma unroll
                for (int nj = 0; nj < 4; ++nj)
                    mma1688(d[mi][nj], af[mi], bf[nj]);
        }
        __syncthreads();

        if (c + 3 < NC) {
            float* dA = sm + b * STAGE_FLOATS;
            float* dB = dA + 2560;
            int k0 = (c + 3) << 4;
            #pragma unroll
            for (int i = 0; i < 2; ++i) {
                int u = i * 256 + t;
                int r = u >> 2, c4 = u & 3;
                cp16(smem_u32(dA + r * PAD + c4 * 4), gA + (size_t)r * K + k0 + c4 * 4);
                cp16(smem_u32(dB + r * PAD + c4 * 4), gB + (size_t)r * K + k0 + c4 * 4);
            }
        }
        asm volatile("cp.async.commit_group;" ::: "memory");
    }

    // epilogue: c0/c1 at (row, col), c2/c3 at (row+8, col); col = 2*lc within tile
    #pragma unroll
    for (int mi = 0; mi < 4; ++mi) {
        #pragma unroll
        for (int nj = 0; nj < 4; ++nj) {
            int row = row0 + wm * 64 + mi * 16 + lr;
            int col = col0 + wn * 32 + nj * 8 + 2 * lc;
            float2 v0 = make_float2(d[mi][nj][0], d[mi][nj][1]);
            float2 v1 = make_float2(d[mi][nj][2], d[mi][nj][3]);
            if (MODE >= 1) {
                float2 bv = *(const float2*)&bias[col];
                v0.x += bv.x; v0.y += bv.y;
                v1.x += bv.x; v1.y += bv.y;
            }
            if (MODE == 1) {
                float2 r0 = *(const float2*)&res[(size_t)row * N + col];
                float2 r1 = *(const float2*)&res[(size_t)(row + 8) * N + col];
                v0.x += r0.x; v0.y += r0.y;
                v1.x += r1.x; v1.y += r1.y;
            }
            if (MODE == 2) {
                v0.x = to_tf32(gelu_exact(v0.x)); v0.y = to_tf32(gelu_exact(v0.y));
                v1.x = to_tf32(gelu_exact(v1.x)); v1.y = to_tf32(gelu_exact(v1.y));
            }
            *(float2*)&C[(size_t)row * N + col]       = v0;
            *(float2*)&C[(size_t)(row + 8) * N + col] = v1;
        }
    }
}

// ---------------- LayerNorm (tf32-rounded output: feeds GEMM A) -------------
__global__ void ln_kernel(const float* __restrict__ x,
                          const float* __restrict__ g,
                          const float* __restrict__ b,
                          float* __restrict__ y) {
    int row = blockIdx.x;
    int t = threadIdx.x;
    const float4* xr = (const float4*)(x + (size_t)row * CDIM);
    float4 v = xr[t];
    float s  = v.x + v.y + v.z + v.w;
    float ss = v.x*v.x + v.y*v.y + v.z*v.z + v.w*v.w;
    #pragma unroll
    for (int off = 16; off > 0; off >>= 1) {
        s  += __shfl_xor_sync(0xffffffffu, s,  off);
        ss += __shfl_xor_sync(0xffffffffu, ss, off);
    }
    __shared__ float sbuf[8], ssbuf[8];
    int warp = t >> 5, lane = t & 31;
    if (lane == 0) { sbuf[warp] = s; ssbuf[warp] = ss; }
    __syncthreads();
    float tot = 0.f, tot2 = 0.f;
    #pragma unroll
    for (int w = 0; w < 8; ++w) { tot += sbuf[w]; tot2 += ssbuf[w]; }
    float mean = tot * (1.0f / CDIM);
    float var  = tot2 * (1.0f / CDIM) - mean * mean;
    float rstd = rsqrtf(var + 1e-5f);
    float4 gg = ((const float4*)g)[t];
    float4 bb = ((const float4*)b)[t];
    float4 o;
    o.x = to_tf32((v.x - mean) * rstd * gg.x + bb.x);
    o.y = to_tf32((v.y - mean) * rstd * gg.y + bb.y);
    o.z = to_tf32((v.z - mean) * rstd * gg.z + bb.z);
    o.w = to_tf32((v.w - mean) * rstd * gg.w + bb.w);
    ((float4*)(y + (size_t)row * CDIM))[t] = o;
}

// ---------------- Flash attention (fp32; output tf32-rounded) ---------------
#define TKV 8
__global__ void __launch_bounds__(128)
attn_kernel(const float* __restrict__ qkv, float* __restrict__ o_out) {
    __shared__ float ks[TKV][68];
    __shared__ float vs[TKV][68];
    const int t  = threadIdx.x;
    const int bh = blockIdx.y;
    const int b  = bh >> 4;
    const int h  = bh & 15;
    const int r  = blockIdx.x * 128 + t;
    const float* qrow = qkv + ((size_t)(b * NSEQ + r)) * (3 * CDIM) + h * HDIM;
    float q[64];
    #pragma unroll
    for (int i = 0; i < 16; ++i) {
        float4 v = *(const float4*)&qrow[i * 4];
        q[i*4+0] = v.x * 0.125f; q[i*4+1] = v.y * 0.125f;
        q[i*4+2] = v.z * 0.125f; q[i*4+3] = v.w * 0.125f;
    }
    float o[64];
    #pragma unroll
    for (int i = 0; i < 64; ++i) o[i] = 0.f;
    float mx = -1e30f, l = 0.f;
    const float* kbase = qkv + ((size_t)b * NSEQ) * (3 * CDIM) + CDIM     + h * HDIM;
    const float* vbase = qkv + ((size_t)b * NSEQ) * (3 * CDIM) + 2 * CDIM + h * HDIM;
    const int jj = t >> 4;
    const int c4 = (t & 15) << 2;
    for (int t0 = 0; t0 < NSEQ; t0 += TKV) {
        __syncthreads();
        *(float4*)&ks[jj][c4] = *(const float4*)&kbase[(size_t)(t0 + jj) * (3 * CDIM) + c4];
        *(float4*)&vs[jj][c4] = *(const float4*)&vbase[(size_t)(t0 + jj) * (3 * CDIM) + c4];
        __syncthreads();
        float s[TKV];
        #pragma unroll
        for (int j = 0; j < TKV; ++j) {
            float a0 = 0.f, a1 = 0.f, a2 = 0.f, a3 = 0.f;
            #pragma unroll
            for (int d = 0; d < 64; d += 4) {
                float4 kk = *(const float4*)&ks[j][d];
                a0 += q[d + 0] * kk.x; a1 += q[d + 1] * kk.y;
                a2 += q[d + 2] * kk.z; a3 += q[d + 3] * kk.w;
            }
            s[j] = (a0 + a1) + (a2 + a3);
        }
        float tmax = s[0];
        #pragma unroll
        for (int j = 1; j < TKV; ++j) tmax = fmaxf(tmax, s[j]);
        float m_new = fmaxf(mx, tmax);
        float corr  = __expf(mx - m_new);
        mx = m_new;
        l *= corr;
        #pragma unroll
        for (int d = 0; d < 64; ++d) o[d] *= corr;
        #pragma unroll
        for (int j = 0; j < TKV; ++j) {
            float p = __expf(s[j] - m_new);
            l += p;
            #pragma unroll
            for (int d = 0; d < 64; d += 4) {
                float4 vv = *(const float4*)&vs[j][d];
                o[d + 0] += p * vv.x; o[d + 1] += p * vv.y;
                o[d + 2] += p * vv.z; o[d + 3] += p * vv.w;
            }
        }
    }
    float inv = 1.0f / l;
    float* orow = o_out + (size_t)(b * NSEQ + r) * CDIM + h * HDIM;
    #pragma unroll
    for (int i = 0; i < 16; ++i) {
        float4 v;
        v.x = to_tf32(o[i*4+0] * inv); v.y = to_tf32(o[i*4+1] * inv);
        v.z = to_tf32(o[i*4+2] * inv); v.w = to_tf32(o[i*4+3] * inv);
        *(float4*)&orow[i * 4] = v;
    }
}

// ---------------- host launch ----------------
extern "C" void kernel_launch(void* const* d_in, const int* in_sizes, int n_in,
                              void* d_out, int out_size) {
    const float* x      = (const float*)d_in[0];
    const float* ln1_g  = (const float*)d_in[1];
    const float* ln1_b  = (const float*)d_in[2];
    const float* w_qkv  = (const float*)d_in[3];
    const float* w_proj = (const float*)d_in[4];
    const float* b_proj = (const float*)d_in[5];
    const float* ln2_g  = (const float*)d_in[6];
    const float* ln2_b  = (const float*)d_in[7];
    const float* w_fc1  = (const float*)d_in[8];
    const float* b_fc1  = (const float*)d_in[9];
    const float* w_fc2  = (const float*)d_in[10];
    const float* b_fc2  = (const float*)d_in[11];
    float* out = (float*)d_out;

    float *h, *qkv, *o, *x1, *h2, *ff;
    float *wqkvT, *wprojT, *wfc1T, *wfc2T;
    cudaGetSymbolAddress((void**)&h,      g_h);
    cudaGetSymbolAddress((void**)&qkv,    g_qkv);
    cudaGetSymbolAddress((void**)&o,      g_o);
    cudaGetSymbolAddress((void**)&x1,     g_x1);
    cudaGetSymbolAddress((void**)&h2,     g_h2);
    cudaGetSymbolAddress((void**)&ff,     g_ff);
    cudaGetSymbolAddress((void**)&wqkvT,  g_wqkvT);
    cudaGetSymbolAddress((void**)&wprojT, g_wprojT);
    cudaGetSymbolAddress((void**)&wfc1T,  g_wfc1T);
    cudaGetSymbolAddress((void**)&wfc2T,  g_wfc2T);

    cudaFuncSetAttribute(gemm_mma<0>, cudaFuncAttributeMaxDynamicSharedMemorySize, GEMM_SMEM);
    cudaFuncSetAttribute(gemm_mma<1>, cudaFuncAttributeMaxDynamicSharedMemorySize, GEMM_SMEM);
    cudaFuncSetAttribute(gemm_mma<2>, cudaFuncAttributeMaxDynamicSharedMemorySize, GEMM_SMEM);

    dim3 tb(32, 8);
    transpose_k<<<dim3(3 * CDIM / 32, CDIM / 32), tb>>>(w_qkv, wqkvT, CDIM, 3 * CDIM);
    transpose_k<<<dim3(CDIM / 32, CDIM / 32), tb>>>(w_proj, wprojT, CDIM, CDIM);
    transpose_k<<<dim3(FFDIM / 32, CDIM / 32), tb>>>(w_fc1, wfc1T, CDIM, FFDIM);
    transpose_k<<<dim3(CDIM / 32, FFDIM / 32), tb>>>(w_fc2, wfc2T, FFDIM, CDIM);

    // 1. LN1
    ln_kernel<<<M_ROWS, 256>>>(x, ln1_g, ln1_b, h);
    // 2. qkv = h @ w_qkv (fp32 out for attention)
    gemm_mma<0><<<dim3(3 * CDIM / 128, M_ROWS / 128), 256, GEMM_SMEM>>>(
        h, wqkvT, nullptr, nullptr, qkv, 3 * CDIM, CDIM);
    // 3. attention
    attn_kernel<<<dim3(NSEQ / 128, 2 * NHEAD), 128>>>(qkv, o);
    // 4. x1 = x + o @ w_proj + b_proj
    gemm_mma<1><<<dim3(CDIM / 128, M_ROWS / 128), 256, GEMM_SMEM>>>(
        o, wprojT, b_proj, x, x1, CDIM, CDIM);
    // 5. LN2
    ln_kernel<<<M_ROWS, 256>>>(x1, ln2_g, ln2_b, h2);
    // 6. ff = tf32(gelu(h2 @ w_fc1 + b_fc1))
    gemm_mma<2><<<dim3(FFDIM / 128, M_ROWS / 128), 256, GEMM_SMEM>>>(
        h2, wfc1T, b_fc1, nullptr, ff, FFDIM, CDIM);
    // 7. out = x1 + ff @ w_fc2 + b_fc2
    gemm_mma<1><<<dim3(CDIM / 128, M_ROWS / 128), 256, GEMM_SMEM>>>(
        ff, wfc2T, b_fc2, x1, out, CDIM, FFDIM);
}

// round 5
// speedup vs baseline: 3.4078x; 1.8817x over previous
#include <cuda_runtime.h>
#include <math.h>
#include <stdint.h>

#define M_ROWS 4096
#define CDIM   1024
#define FFDIM  4096
#define NSEQ   2048
#define NHEAD  16
#define HDIM   64

// ---------------- scratch (device globals; no allocs allowed) ----------------
__device__ float g_h  [M_ROWS * CDIM];
__device__ float g_qkv[M_ROWS * 3 * CDIM];
__device__ float g_o  [M_ROWS * CDIM];
__device__ float g_x1 [M_ROWS * CDIM];
__device__ float g_h2 [M_ROWS * CDIM];
__device__ float g_ff [M_ROWS * FFDIM];
__device__ float g_wqkvT[3 * CDIM * CDIM];
__device__ float g_wprojT[CDIM * CDIM];
__device__ float g_wfc1T[FFDIM * CDIM];
__device__ float g_wfc2T[CDIM * FFDIM];

// ---------------- helpers ----------------
__device__ __forceinline__ uint32_t smem_u32(const void* p) {
    uint32_t a;
    asm("{ .reg .u64 t; cvta.to.shared.u64 t, %1; cvt.u32.u64 %0, t; }" : "=r"(a) : "l"(p));
    return a;
}
__device__ __forceinline__ void cp16(uint32_t s, const void* g) {
    asm volatile("cp.async.cg.shared.global [%0], [%1], 16;" :: "r"(s), "l"(g) : "memory");
}
__device__ __forceinline__ float to_tf32(float v) {
    uint32_t u;
    asm("cvt.rna.tf32.f32 %0, %1;" : "=r"(u) : "f"(v));
    return __uint_as_float(u);
}
__device__ __forceinline__ uint32_t to_tf32u(float v) {
    uint32_t u;
    asm("cvt.rna.tf32.f32 %0, %1;" : "=r"(u) : "f"(v));
    return u;
}
__device__ __forceinline__ void mma1688(float* d, const uint32_t* a, const uint32_t* b) {
    asm volatile(
        "mma.sync.aligned.m16n8k8.row.col.f32.tf32.tf32.f32 "
        "{%0,%1,%2,%3}, {%4,%5,%6,%7}, {%8,%9}, {%0,%1,%2,%3};"
        : "+f"(d[0]), "+f"(d[1]), "+f"(d[2]), "+f"(d[3])
        : "r"(a[0]), "r"(a[1]), "r"(a[2]), "r"(a[3]), "r"(b[0]), "r"(b[1]));
}
__device__ __forceinline__ float gelu_exact(float v) {
    return 0.5f * v * (1.0f + erff(v * 0.70710678118654752f));
}

// ---------------- weight transpose + tf32 round: in[K,N] -> out[N,K] --------
__global__ void transpose_k(const float* __restrict__ in, float* __restrict__ out,
                            int K, int N) {
    __shared__ float tile[32][33];
    int tx = threadIdx.x, ty = threadIdx.y;
    int x = blockIdx.x * 32 + tx;
    int y0 = blockIdx.y * 32;
    #pragma unroll
    for (int j = 0; j < 32; j += 8)
        tile[ty + j][tx] = in[(size_t)(y0 + ty + j) * N + x];
    __syncthreads();
    int ox = y0 + tx;
    int oy0 = blockIdx.x * 32;
    #pragma unroll
    for (int j = 0; j < 32; j += 8)
        out[(size_t)(oy0 + ty + j) * K + ox] = to_tf32(tile[tx][ty + j]);
}

// ---------------- mma.sync tf32 GEMM (unchanged from R3) ----------------
#define PAD 20
#define STAGE_FLOATS 5120
#define GEMM_SMEM (3 * STAGE_FLOATS * 4)

template <int MODE>
__global__ void __launch_bounds__(256)
gemm_mma(const float* __restrict__ A, const float* __restrict__ BT,
         const float* __restrict__ bias, const float* __restrict__ res,
         float* __restrict__ C, int N, int K) {
    extern __shared__ float sm[];
    const int t = threadIdx.x;
    const int lane = t & 31;
    const int wid = t >> 5;
    const int wm = wid >> 2;
    const int wn = wid & 3;
    const int lr = lane >> 2;
    const int lc = lane & 3;
    const int row0 = blockIdx.y * 128, col0 = blockIdx.x * 128;
    const float* gA = A + (size_t)row0 * K;
    const float* gB = BT + (size_t)col0 * K;
    const int NC = K >> 4;

    float d[4][4][4];
    #pragma unroll
    for (int i = 0; i < 4; ++i)
        #pragma unroll
        for (int j = 0; j < 4; ++j)
            #pragma unroll
            for (int e = 0; e < 4; ++e) d[i][j][e] = 0.f;

    #pragma unroll
    for (int s = 0; s < 3; ++s) {
        float* dA = sm + s * STAGE_FLOATS;
        float* dB = dA + 2560;
        int k0 = s << 4;
        #pragma unroll
        for (int i = 0; i < 2; ++i) {
            int u = i * 256 + t;
            int r = u >> 2, c4 = u & 3;
            cp16(smem_u32(dA + r * PAD + c4 * 4), gA + (size_t)r * K + k0 + c4 * 4);
            cp16(smem_u32(dB + r * PAD + c4 * 4), gB + (size_t)r * K + k0 + c4 * 4);
        }
        asm volatile("cp.async.commit_group;" ::: "memory");
    }

    for (int c = 0; c < NC; ++c) {
        int b = c % 3;
        asm volatile("cp.async.wait_group 2;" ::: "memory");
        __syncthreads();

        const float* As = sm + b * STAGE_FLOATS;
        const float* Bs = As + 2560;
        #pragma unroll
        for (int s = 0; s < 2; ++s) {
            uint32_t af[4][4], bf[4][2];
            #pragma unroll
            for (int mi = 0; mi < 4; ++mi) {
                const float* p = As + (wm * 64 + mi * 16 + lr) * PAD + s * 8 + lc;
                af[mi][0] = __float_as_uint(p[0]);
                af[mi][1] = __float_as_uint(p[8 * PAD]);
                af[mi][2] = __float_as_uint(p[4]);
                af[mi][3] = __float_as_uint(p[8 * PAD + 4]);
            }
            #pragma unroll
            for (int nj = 0; nj < 4; ++nj) {
                const float* q = Bs + (wn * 32 + nj * 8 + lr) * PAD + s * 8 + lc;
                bf[nj][0] = __float_as_uint(q[0]);
                bf[nj][1] = __float_as_uint(q[4]);
            }
            #pragma unroll
            for (int mi = 0; mi < 4; ++mi)
                #pragma unroll
                for (int nj = 0; nj < 4; ++nj)
                    mma1688(d[mi][nj], af[mi], bf[nj]);
        }
        __syncthreads();

        if (c + 3 < NC) {
            float* dA = sm + b * STAGE_FLOATS;
            float* dB = dA + 2560;
            int k0 = (c + 3) << 4;
            #pragma unroll
            for (int i = 0; i < 2; ++i) {
                int u = i * 256 + t;
                int r = u >> 2, c4 = u & 3;
                cp16(smem_u32(dA + r * PAD + c4 * 4), gA + (size_t)r * K + k0 + c4 * 4);
                cp16(smem_u32(dB + r * PAD + c4 * 4), gB + (size_t)r * K + k0 + c4 * 4);
            }
        }
        asm volatile("cp.async.commit_group;" ::: "memory");
    }

    #pragma unroll
    for (int mi = 0; mi < 4; ++mi) {
        #pragma unroll
        for (int nj = 0; nj < 4; ++nj) {
            int row = row0 + wm * 64 + mi * 16 + lr;
            int col = col0 + wn * 32 + nj * 8 + 2 * lc;
            float2 v0 = make_float2(d[mi][nj][0], d[mi][nj][1]);
            float2 v1 = make_float2(d[mi][nj][2], d[mi][nj][3]);
            if (MODE >= 1) {
                float2 bv = *(const float2*)&bias[col];
                v0.x += bv.x; v0.y += bv.y;
                v1.x += bv.x; v1.y += bv.y;
            }
            if (MODE == 1) {
                float2 r0 = *(const float2*)&res[(size_t)row * N + col];
                float2 r1 = *(const float2*)&res[(size_t)(row + 8) * N + col];
                v0.x += r0.x; v0.y += r0.y;
                v1.x += r1.x; v1.y += r1.y;
            }
            if (MODE == 2) {
                v0.x = to_tf32(gelu_exact(v0.x)); v0.y = to_tf32(gelu_exact(v0.y));
                v1.x = to_tf32(gelu_exact(v1.x)); v1.y = to_tf32(gelu_exact(v1.y));
            }
            *(float2*)&C[(size_t)row * N + col]       = v0;
            *(float2*)&C[(size_t)(row + 8) * N + col] = v1;
        }
    }
}

// ---------------- LayerNorm (tf32-rounded output) ----------------
__global__ void ln_kernel(const float* __restrict__ x,
                          const float* __restrict__ g,
                          const float* __restrict__ b,
                          float* __restrict__ y) {
    int row = blockIdx.x;
    int t = threadIdx.x;
    const float4* xr = (const float4*)(x + (size_t)row * CDIM);
    float4 v = xr[t];
    float s  = v.x + v.y + v.z + v.w;
    float ss = v.x*v.x + v.y*v.y + v.z*v.z + v.w*v.w;
    #pragma unroll
    for (int off = 16; off > 0; off >>= 1) {
        s  += __shfl_xor_sync(0xffffffffu, s,  off);
        ss += __shfl_xor_sync(0xffffffffu, ss, off);
    }
    __shared__ float sbuf[8], ssbuf[8];
    int warp = t >> 5, lane = t & 31;
    if (lane == 0) { sbuf[warp] = s; ssbuf[warp] = ss; }
    __syncthreads();
    float tot = 0.f, tot2 = 0.f;
    #pragma unroll
    for (int w = 0; w < 8; ++w) { tot += sbuf[w]; tot2 += ssbuf[w]; }
    float mean = tot * (1.0f / CDIM);
    float var  = tot2 * (1.0f / CDIM) - mean * mean;
    float rstd = rsqrtf(var + 1e-5f);
    float4 gg = ((const float4*)g)[t];
    float4 bb = ((const float4*)b)[t];
    float4 o;
    o.x = to_tf32((v.x - mean) * rstd * gg.x + bb.x);
    o.y = to_tf32((v.y - mean) * rstd * gg.y + bb.y);
    o.z = to_tf32((v.z - mean) * rstd * gg.z + bb.z);
    o.w = to_tf32((v.w - mean) * rstd * gg.w + bb.w);
    ((float4*)(y + (size_t)row * CDIM))[t] = o;
}

// ---------------- Tensor-core flash attention ----------------
// Grid (16, 32), 256 threads (8 warps). Warp w handles q-rows [w*16, w*16+16).
// KV chunks of 64, double-buffered cp.async (FIXED: full 64-col tile load).
#define KCH  64
#define KPAD 68
#define VPAD 72
#define AT_SMEM ((2 * KCH * KPAD + 2 * KCH * VPAD) * 4)

__global__ void __launch_bounds__(256)
attn_mma(const float* __restrict__ qkv, float* __restrict__ o_out) {
    extern __shared__ float as_[];
    float* Ks = as_;                         // [2][64][KPAD]
    float* Vs = as_ + 2 * KCH * KPAD;        // [2][64][VPAD]

    const int t = threadIdx.x, lane = t & 31, w = t >> 5;
    const int lr = lane >> 2, lc = lane & 3;
    const int bh = blockIdx.y, b = bh >> 4, h = bh & 15;
    const int qrow0 = blockIdx.x * 128 + w * 16;

    const float* kbase = qkv + (size_t)b * NSEQ * (3 * CDIM) + CDIM     + h * HDIM;
    const float* vbase = qkv + (size_t)b * NSEQ * (3 * CDIM) + 2 * CDIM + h * HDIM;

    // Q fragments (A layout), pre-scaled + tf32
    uint32_t qa[8][4];
    {
        const float* q0 = qkv + (size_t)(b * NSEQ + qrow0) * (3 * CDIM) + h * HDIM;
        #pragma unroll
        for (int kk = 0; kk < 8; ++kk) {
            qa[kk][0] = to_tf32u(q0[(size_t)lr * (3*CDIM)       + kk*8 + lc]     * 0.125f);
            qa[kk][1] = to_tf32u(q0[(size_t)(lr+8) * (3*CDIM)   + kk*8 + lc]     * 0.125f);
            qa[kk][2] = to_tf32u(q0[(size_t)lr * (3*CDIM)       + kk*8 + lc + 4] * 0.125f);
            qa[kk][3] = to_tf32u(q0[(size_t)(lr+8) * (3*CDIM)   + kk*8 + lc + 4] * 0.125f);
        }
    }

    float o[8][4];
    #pragma unroll
    for (int i = 0; i < 8; ++i) { o[i][0]=0.f; o[i][1]=0.f; o[i][2]=0.f; o[i][3]=0.f; }
    float m0 = -1e30f, m1 = -1e30f, l0 = 0.f, l1 = 0.f;

    // tile load geometry: 64 rows x 16 segments(16B) = 1024 units, 4 per thread
    // prefetch chunk 0 into buf 0
    #pragma unroll
    for (int i = 0; i < 4; ++i) {
        int u = i * 256 + t;
        int r = u >> 4, seg = u & 15;
        cp16(smem_u32(Ks + r * KPAD + seg * 4), kbase + (size_t)r * (3*CDIM) + seg * 4);
        cp16(smem_u32(Vs + r * VPAD + seg * 4), vbase + (size_t)r * (3*CDIM) + seg * 4);
    }
    asm volatile("cp.async.commit_group;" ::: "memory");

    const int NCH = NSEQ / KCH;   // 32
    for (int c = 0; c < NCH; ++c) {
        int buf = c & 1;
        if (c + 1 < NCH) {
            int nb = (c + 1) & 1;
            #pragma unroll
            for (int i = 0; i < 4; ++i) {
                int u = i * 256 + t;
                int r = u >> 4, seg = u & 15;
                const float* ksrc = kbase + (size_t)((c+1) * KCH + r) * (3*CDIM) + seg * 4;
                const float* vsrc = vbase + (size_t)((c+1) * KCH + r) * (3*CDIM) + seg * 4;
                cp16(smem_u32(Ks + nb * KCH * KPAD + r * KPAD + seg * 4), ksrc);
                cp16(smem_u32(Vs + nb * KCH * VPAD + r * VPAD + seg * 4), vsrc);
            }
            asm volatile("cp.async.commit_group;" ::: "memory");
            asm volatile("cp.async.wait_group 1;" ::: "memory");
        } else {
            asm volatile("cp.async.wait_group 0;" ::: "memory");
        }
        __syncthreads();

        const float* Kb = Ks + buf * KCH * KPAD;
        const float* Vb = Vs + buf * KCH * VPAD;

        // S = Q @ K^T for this 16x64 strip
        float s[8][4];
        #pragma unroll
        for (int nj = 0; nj < 8; ++nj) { s[nj][0]=0.f; s[nj][1]=0.f; s[nj][2]=0.f; s[nj][3]=0.f; }
        #pragma unroll
        for (int nj = 0; nj < 8; ++nj) {
            #pragma unroll
            for (int kk = 0; kk < 8; ++kk) {
                uint32_t bf[2];
                bf[0] = __float_as_uint(Kb[(nj*8 + lr) * KPAD + kk*8 + lc]);
                bf[1] = __float_as_uint(Kb[(nj*8 + lr) * KPAD + kk*8 + lc + 4]);
                mma1688(s[nj], qa[kk], bf);
            }
        }

        // online softmax (rows lr and lr+8)
        float rmax0 = -1e30f, rmax1 = -1e30f;
        #pragma unroll
        for (int nj = 0; nj < 8; ++nj) {
            rmax0 = fmaxf(rmax0, fmaxf(s[nj][0], s[nj][1]));
            rmax1 = fmaxf(rmax1, fmaxf(s[nj][2], s[nj][3]));
        }
        rmax0 = fmaxf(rmax0, __shfl_xor_sync(0xffffffffu, rmax0, 1));
        rmax0 = fmaxf(rmax0, __shfl_xor_sync(0xffffffffu, rmax0, 2));
        rmax1 = fmaxf(rmax1, __shfl_xor_sync(0xffffffffu, rmax1, 1));
        rmax1 = fmaxf(rmax1, __shfl_xor_sync(0xffffffffu, rmax1, 2));
        float mn0 = fmaxf(m0, rmax0), mn1 = fmaxf(m1, rmax1);
        float corr0 = __expf(m0 - mn0), corr1 = __expf(m1 - mn1);
        m0 = mn0; m1 = mn1;

        float ls0 = 0.f, ls1 = 0.f;
        #pragma unroll
        for (int nj = 0; nj < 8; ++nj) {
            s[nj][0] = __expf(s[nj][0] - mn0);
            s[nj][1] = __expf(s[nj][1] - mn0);
            s[nj][2] = __expf(s[nj][2] - mn1);
            s[nj][3] = __expf(s[nj][3] - mn1);
            ls0 += s[nj][0] + s[nj][1];
            ls1 += s[nj][2] + s[nj][3];
        }
        ls0 += __shfl_xor_sync(0xffffffffu, ls0, 1);
        ls0 += __shfl_xor_sync(0xffffffffu, ls0, 2);
        ls1 += __shfl_xor_sync(0xffffffffu, ls1, 1);
        ls1 += __shfl_xor_sync(0xffffffffu, ls1, 2);
        l0 = l0 * corr0 + ls0;
        l1 = l1 * corr1 + ls1;

        #pragma unroll
        for (int nj = 0; nj < 8; ++nj) {
            o[nj][0] *= corr0; o[nj][1] *= corr0;
            o[nj][2] *= corr1; o[nj][3] *= corr1;
        }

        // O += P @ V : re-fragment P (C-layout -> A-layout) via shuffles
        #pragma unroll
        for (int kk2 = 0; kk2 < 8; ++kk2) {
            int sl = lr * 4 + (lc >> 1);
            float v00 = __shfl_sync(0xffffffffu, s[kk2][0], sl);
            float v01 = __shfl_sync(0xffffffffu, s[kk2][1], sl);
            float v20 = __shfl_sync(0xffffffffu, s[kk2][2], sl);
            float v21 = __shfl_sync(0xffffffffu, s[kk2][3], sl);
            float w00 = __shfl_sync(0xffffffffu, s[kk2][0], sl + 2);
            float w01 = __shfl_sync(0xffffffffu, s[kk2][1], sl + 2);
            float w20 = __shfl_sync(0xffffffffu, s[kk2][2], sl + 2);
            float w21 = __shfl_sync(0xffffffffu, s[kk2][3], sl + 2);
            uint32_t pa[4];
            bool odd = (lc & 1);
            pa[0] = to_tf32u(odd ? v01 : v00);
            pa[1] = to_tf32u(odd ? v21 : v20);
            pa[2] = to_tf32u(odd ? w01 : w00);
            pa[3] = to_tf32u(odd ? w21 : w20);
            #pragma unroll
            for (int nj2 = 0; nj2 < 8; ++nj2) {
                uint32_t bf[2];
                bf[0] = __float_as_uint(Vb[(kk2*8 + lc) * VPAD + nj2*8 + lr]);
                bf[1] = __float_as_uint(Vb[(kk2*8 + lc + 4) * VPAD + nj2*8 + lr]);
                mma1688(o[nj2], pa, bf);
            }
        }
        __syncthreads();
    }

    // write output (tf32-rounded: feeds proj GEMM A operand)
    float inv0 = 1.0f / l0, inv1 = 1.0f / l1;
    size_t row = (size_t)(b * NSEQ + qrow0 + lr);
    #pragma unroll
    for (int nj2 = 0; nj2 < 8; ++nj2) {
        int col = h * HDIM + nj2 * 8 + 2 * lc;
        float2 v0 = make_float2(to_tf32(o[nj2][0] * inv0), to_tf32(o[nj2][1] * inv0));
        float2 v1 = make_float2(to_tf32(o[nj2][2] * inv1), to_tf32(o[nj2][3] * inv1));
        *(float2*)&o_out[row * CDIM + col]       = v0;
        *(float2*)&o_out[(row + 8) * CDIM + col] = v1;
    }
}

// ---------------- host launch ----------------
extern "C" void kernel_launch(void* const* d_in, const int* in_sizes, int n_in,
                              void* d_out, int out_size) {
    const float* x      = (const float*)d_in[0];
    const float* ln1_g  = (const float*)d_in[1];
    const float* ln1_b  = (const float*)d_in[2];
    const float* w_qkv  = (const float*)d_in[3];
    const float* w_proj = (const float*)d_in[4];
    const float* b_proj = (const float*)d_in[5];
    const float* ln2_g  = (const float*)d_in[6];
    const float* ln2_b  = (const float*)d_in[7];
    const float* w_fc1  = (const float*)d_in[8];
    const float* b_fc1  = (const float*)d_in[9];
    const float* w_fc2  = (const float*)d_in[10];
    const float* b_fc2  = (const float*)d_in[11];
    float* out = (float*)d_out;

    float *h, *qkv, *o, *x1, *h2, *ff;
    float *wqkvT, *wprojT, *wfc1T, *wfc2T;
    cudaGetSymbolAddress((void**)&h,      g_h);
    cudaGetSymbolAddress((void**)&qkv,    g_qkv);
    cudaGetSymbolAddress((void**)&o,      g_o);
    cudaGetSymbolAddress((void**)&x1,     g_x1);
    cudaGetSymbolAddress((void**)&h2,     g_h2);
    cudaGetSymbolAddress((void**)&ff,     g_ff);
    cudaGetSymbolAddress((void**)&wqkvT,  g_wqkvT);
    cudaGetSymbolAddress((void**)&wprojT, g_wprojT);
    cudaGetSymbolAddress((void**)&wfc1T,  g_wfc1T);
    cudaGetSymbolAddress((void**)&wfc2T,  g_wfc2T);

    cudaFuncSetAttribute(gemm_mma<0>, cudaFuncAttributeMaxDynamicSharedMemorySize, GEMM_SMEM);
    cudaFuncSetAttribute(gemm_mma<1>, cudaFuncAttributeMaxDynamicSharedMemorySize, GEMM_SMEM);
    cudaFuncSetAttribute(gemm_mma<2>, cudaFuncAttributeMaxDynamicSharedMemorySize, GEMM_SMEM);
    cudaFuncSetAttribute(attn_mma,    cudaFuncAttributeMaxDynamicSharedMemorySize, AT_SMEM);

    dim3 tb(32, 8);
    transpose_k<<<dim3(3 * CDIM / 32, CDIM / 32), tb>>>(w_qkv, wqkvT, CDIM, 3 * CDIM);
    transpose_k<<<dim3(CDIM / 32, CDIM / 32), tb>>>(w_proj, wprojT, CDIM, CDIM);
    transpose_k<<<dim3(FFDIM / 32, CDIM / 32), tb>>>(w_fc1, wfc1T, CDIM, FFDIM);
    transpose_k<<<dim3(CDIM / 32, FFDIM / 32), tb>>>(w_fc2, wfc2T, FFDIM, CDIM);

    // 1. LN1
    ln_kernel<<<M_ROWS, 256>>>(x, ln1_g, ln1_b, h);
    // 2. qkv = h @ w_qkv (fp32 out for attention)
    gemm_mma<0><<<dim3(3 * CDIM / 128, M_ROWS / 128), 256, GEMM_SMEM>>>(
        h, wqkvT, nullptr, nullptr, qkv, 3 * CDIM, CDIM);
    // 3. attention (tensor core flash)
    attn_mma<<<dim3(NSEQ / 128, 2 * NHEAD), 256, AT_SMEM>>>(qkv, o);
    // 4. x1 = x + o @ w_proj + b_proj
    gemm_mma<1><<<dim3(CDIM / 128, M_ROWS / 128), 256, GEMM_SMEM>>>(
        o, wprojT, b_proj, x, x1, CDIM, CDIM);
    // 5. LN2
    ln_kernel<<<M_ROWS, 256>>>(x1, ln2_g, ln2_b, h2);
    // 6. ff = tf32(gelu(h2 @ w_fc1 + b_fc1))
    gemm_mma<2><<<dim3(FFDIM / 128, M_ROWS / 128), 256, GEMM_SMEM>>>(
        h2, wfc1T, b_fc1, nullptr, ff, FFDIM, CDIM);
    // 7. out = x1 + ff @ w_fc2 + b_fc2
    gemm_mma<1><<<dim3(CDIM / 128, M_ROWS / 128), 256, GEMM_SMEM>>>(
        ff, wfc2T, b_fc2, x1, out, CDIM, FFDIM);
}

// round 6
// speedup vs baseline: 5.0883x; 1.4931x over previous
#include <cuda_runtime.h>
#include <cuda_fp16.h>
#include <math.h>
#include <stdint.h>

#define M_ROWS 4096
#define CDIM   1024
#define FFDIM  4096
#define NSEQ   2048
#define NHEAD  16
#define HDIM   64

// ---------------- scratch (device globals; no allocs allowed) ----------------
__device__ __half g_h  [M_ROWS * CDIM];      // LN1 out (fp16)
__device__ float  g_qkv[M_ROWS * 3 * CDIM];  // fp32 (attention input)
__device__ __half g_o  [M_ROWS * CDIM];      // attn out (fp16)
__device__ float  g_x1 [M_ROWS * CDIM];      // post-attn residual (fp32)
__device__ __half g_h2 [M_ROWS * CDIM];      // LN2 out (fp16)
__device__ __half g_ff [M_ROWS * FFDIM];     // gelu(fc1) (fp16)
__device__ __half g_wqkvT[3 * CDIM * CDIM];
__device__ __half g_wprojT[CDIM * CDIM];
__device__ __half g_wfc1T[FFDIM * CDIM];
__device__ __half g_wfc2T[CDIM * FFDIM];

// ---------------- helpers ----------------
__device__ __forceinline__ uint32_t smem_u32(const void* p) {
    uint32_t a;
    asm("{ .reg .u64 t; cvta.to.shared.u64 t, %1; cvt.u32.u64 %0, t; }" : "=r"(a) : "l"(p));
    return a;
}
__device__ __forceinline__ void cp16(uint32_t s, const void* g) {
    asm volatile("cp.async.cg.shared.global [%0], [%1], 16;" :: "r"(s), "l"(g) : "memory");
}
__device__ __forceinline__ float to_tf32(float v) {
    uint32_t u;
    asm("cvt.rna.tf32.f32 %0, %1;" : "=r"(u) : "f"(v));
    return __uint_as_float(u);
}
__device__ __forceinline__ uint32_t to_tf32u(float v) {
    uint32_t u;
    asm("cvt.rna.tf32.f32 %0, %1;" : "=r"(u) : "f"(v));
    return u;
}
__device__ __forceinline__ void mma1688(float* d, const uint32_t* a, const uint32_t* b) {
    asm volatile(
        "mma.sync.aligned.m16n8k8.row.col.f32.tf32.tf32.f32 "
        "{%0,%1,%2,%3}, {%4,%5,%6,%7}, {%8,%9}, {%0,%1,%2,%3};"
        : "+f"(d[0]), "+f"(d[1]), "+f"(d[2]), "+f"(d[3])
        : "r"(a[0]), "r"(a[1]), "r"(a[2]), "r"(a[3]), "r"(b[0]), "r"(b[1]));
}
__device__ __forceinline__ void mma16816(float* d, const uint32_t* a, const uint32_t* b) {
    asm volatile(
        "mma.sync.aligned.m16n8k16.row.col.f32.f16.f16.f32 "
        "{%0,%1,%2,%3}, {%4,%5,%6,%7}, {%8,%9}, {%0,%1,%2,%3};"
        : "+f"(d[0]), "+f"(d[1]), "+f"(d[2]), "+f"(d[3])
        : "r"(a[0]), "r"(a[1]), "r"(a[2]), "r"(a[3]), "r"(b[0]), "r"(b[1]));
}
__device__ __forceinline__ float gelu_exact(float v) {
    return 0.5f * v * (1.0f + erff(v * 0.70710678118654752f));
}

// ---------------- weight transpose + fp16 convert: in[K,N] -> out[N,K] ------
__global__ void transpose_k(const float* __restrict__ in, __half* __restrict__ out,
                            int K, int N) {
    __shared__ float tile[32][33];
    int tx = threadIdx.x, ty = threadIdx.y;
    int x = blockIdx.x * 32 + tx;
    int y0 = blockIdx.y * 32;
    #pragma unroll
    for (int j = 0; j < 32; j += 8)
        tile[ty + j][tx] = in[(size_t)(y0 + ty + j) * N + x];
    __syncthreads();
    int ox = y0 + tx;
    int oy0 = blockIdx.x * 32;
    #pragma unroll
    for (int j = 0; j < 32; j += 8)
        out[(size_t)(oy0 + ty + j) * K + ox] = __float2half_rn(tile[tx][ty + j]);
}

// ---------------- fp16 m16n8k16 GEMM ----------------
// C[4096, N] = A[4096, K] @ BT[N, K]^T ; A, BT fp16; accum fp32.
// CTA 128x128, 8 warps (2x4), warp 64x32, k-chunk 32, 3-stage cp.async.
// MODE 0: fp32 out   MODE 1: fp32 out +bias +res   MODE 2: fp16 out gelu(+bias)
#define PADH 40
#define STAGE_H (2 * 128 * PADH)            // 10240 halfs per stage (A+B)
#define GEMM_SMEM (3 * STAGE_H * 2)         // 61440 bytes

template <int MODE>
__global__ void __launch_bounds__(256)
gemm_h(const __half* __restrict__ A, const __half* __restrict__ BT,
       const float* __restrict__ bias, const float* __restrict__ res,
       void* __restrict__ Cv, int N, int K) {
    extern __shared__ __half smh[];
    const int t = threadIdx.x;
    const int lane = t & 31;
    const int wid = t >> 5;
    const int wm = wid >> 2;          // 0..1
    const int wn = wid & 3;           // 0..3
    const int lr = lane >> 2;         // 0..7
    const int lc = lane & 3;          // 0..3
    const int row0 = blockIdx.y * 128, col0 = blockIdx.x * 128;
    const __half* gA = A + (size_t)row0 * K;
    const __half* gB = BT + (size_t)col0 * K;
    const int NC = K >> 5;            // chunks of 32

    float d[4][4][4];
    #pragma unroll
    for (int i = 0; i < 4; ++i)
        #pragma unroll
        for (int j = 0; j < 4; ++j)
            #pragma unroll
            for (int e = 0; e < 4; ++e) d[i][j][e] = 0.f;

    // prologue: 3 stages. Tile = 128 rows x 32 halfs = 4 x 16B segments/row.
    #pragma unroll
    for (int s = 0; s < 3; ++s) {
        __half* dA = smh + s * STAGE_H;
        __half* dB = dA + 128 * PADH;
        int k0 = s << 5;
        #pragma unroll
        for (int i = 0; i < 2; ++i) {
            int u = i * 256 + t;          // 0..511
            int r = u >> 2, seg = u & 3;
            cp16(smem_u32(dA + r * PADH + seg * 8), gA + (size_t)r * K + k0 + seg * 8);
            cp16(smem_u32(dB + r * PADH + seg * 8), gB + (size_t)r * K + k0 + seg * 8);
        }
        asm volatile("cp.async.commit_group;" ::: "memory");
    }

    for (int c = 0; c < NC; ++c) {
        int b = c % 3;
        asm volatile("cp.async.wait_group 2;" ::: "memory");
        __syncthreads();

        const __half* As = smh + b * STAGE_H;
        const __half* Bs = As + 128 * PADH;
        #pragma unroll
        for (int s = 0; s < 2; ++s) {           // two k16 steps
            uint32_t af[4][4], bf[4][2];
            #pragma unroll
            for (int mi = 0; mi < 4; ++mi) {
                const __half* p = As + (wm * 64 + mi * 16 + lr) * PADH + s * 16 + 2 * lc;
                af[mi][0] = *(const uint32_t*)p;
                af[mi][1] = *(const uint32_t*)(p + 8 * PADH);
                af[mi][2] = *(const uint32_t*)(p + 8);
                af[mi][3] = *(const uint32_t*)(p + 8 * PADH + 8);
            }
            #pragma unroll
            for (int nj = 0; nj < 4; ++nj) {
                const __half* q = Bs + (wn * 32 + nj * 8 + lr) * PADH + s * 16 + 2 * lc;
                bf[nj][0] = *(const uint32_t*)q;
                bf[nj][1] = *(const uint32_t*)(q + 8);
            }
            #pragma unroll
            for (int mi = 0; mi < 4; ++mi)
                #pragma unroll
                for (int nj = 0; nj < 4; ++nj)
                    mma16816(d[mi][nj], af[mi], bf[nj]);
        }
        __syncthreads();

        if (c + 3 < NC) {
            __half* dA = smh + b * STAGE_H;
            __half* dB = dA + 128 * PADH;
            int k0 = (c + 3) << 5;
            #pragma unroll
            for (int i = 0; i < 2; ++i) {
                int u = i * 256 + t;
                int r = u >> 2, seg = u & 3;
                cp16(smem_u32(dA + r * PADH + seg * 8), gA + (size_t)r * K + k0 + seg * 8);
                cp16(smem_u32(dB + r * PADH + seg * 8), gB + (size_t)r * K + k0 + seg * 8);
            }
        }
        asm volatile("cp.async.commit_group;" ::: "memory");
    }

    // epilogue
    #pragma unroll
    for (int mi = 0; mi < 4; ++mi) {
        #pragma unroll
        for (int nj = 0; nj < 4; ++nj) {
            int row = row0 + wm * 64 + mi * 16 + lr;
            int col = col0 + wn * 32 + nj * 8 + 2 * lc;
            float2 v0 = make_float2(d[mi][nj][0], d[mi][nj][1]);
            float2 v1 = make_float2(d[mi][nj][2], d[mi][nj][3]);
            if (MODE >= 1) {
                float2 bv = *(const float2*)&bias[col];
                v0.x += bv.x; v0.y += bv.y;
                v1.x += bv.x; v1.y += bv.y;
            }
            if (MODE == 1) {
                float* Cf = (float*)Cv;
                float2 r0 = *(const float2*)&res[(size_t)row * N + col];
                float2 r1 = *(const float2*)&res[(size_t)(row + 8) * N + col];
                v0.x += r0.x; v0.y += r0.y;
                v1.x += r1.x; v1.y += r1.y;
                *(float2*)&Cf[(size_t)row * N + col]       = v0;
                *(float2*)&Cf[(size_t)(row + 8) * N + col] = v1;
            } else if (MODE == 2) {
                __half* Ch = (__half*)Cv;
                __half2 h0 = __floats2half2_rn(gelu_exact(v0.x), gelu_exact(v0.y));
                __half2 h1 = __floats2half2_rn(gelu_exact(v1.x), gelu_exact(v1.y));
                *(__half2*)&Ch[(size_t)row * N + col]       = h0;
                *(__half2*)&Ch[(size_t)(row + 8) * N + col] = h1;
            } else {
                float* Cf = (float*)Cv;
                *(float2*)&Cf[(size_t)row * N + col]       = v0;
                *(float2*)&Cf[(size_t)(row + 8) * N + col] = v1;
            }
        }
    }
}

// ---------------- LayerNorm (fp16 output: feeds GEMM A) ----------------
__global__ void ln_kernel(const float* __restrict__ x,
                          const float* __restrict__ g,
                          const float* __restrict__ b,
                          __half* __restrict__ y) {
    int row = blockIdx.x;
    int t = threadIdx.x;
    const float4* xr = (const float4*)(x + (size_t)row * CDIM);
    float4 v = xr[t];
    float s  = v.x + v.y + v.z + v.w;
    float ss = v.x*v.x + v.y*v.y + v.z*v.z + v.w*v.w;
    #pragma unroll
    for (int off = 16; off > 0; off >>= 1) {
        s  += __shfl_xor_sync(0xffffffffu, s,  off);
        ss += __shfl_xor_sync(0xffffffffu, ss, off);
    }
    __shared__ float sbuf[8], ssbuf[8];
    int warp = t >> 5, lane = t & 31;
    if (lane == 0) { sbuf[warp] = s; ssbuf[warp] = ss; }
    __syncthreads();
    float tot = 0.f, tot2 = 0.f;
    #pragma unroll
    for (int w = 0; w < 8; ++w) { tot += sbuf[w]; tot2 += ssbuf[w]; }
    float mean = tot * (1.0f / CDIM);
    float var  = tot2 * (1.0f / CDIM) - mean * mean;
    float rstd = rsqrtf(var + 1e-5f);
    float4 gg = ((const float4*)g)[t];
    float4 bb = ((const float4*)b)[t];
    __half2 h0 = __floats2half2_rn((v.x - mean) * rstd * gg.x + bb.x,
                                   (v.y - mean) * rstd * gg.y + bb.y);
    __half2 h1 = __floats2half2_rn((v.z - mean) * rstd * gg.z + bb.z,
                                   (v.w - mean) * rstd * gg.w + bb.w);
    __half2* yp = (__half2*)(y + (size_t)row * CDIM + t * 4);
    yp[0] = h0;
    yp[1] = h1;
}

// ---------------- Tensor-core flash attention (tf32, unchanged core) --------
// fp16 output (feeds proj GEMM A).
#define KCH  64
#define KPAD 68
#define VPAD 72
#define AT_SMEM ((2 * KCH * KPAD + 2 * KCH * VPAD) * 4)

__global__ void __launch_bounds__(256)
attn_mma(const float* __restrict__ qkv, __half* __restrict__ o_out) {
    extern __shared__ float as_[];
    float* Ks = as_;                         // [2][64][KPAD]
    float* Vs = as_ + 2 * KCH * KPAD;        // [2][64][VPAD]

    const int t = threadIdx.x, lane = t & 31, w = t >> 5;
    const int lr = lane >> 2, lc = lane & 3;
    const int bh = blockIdx.y, b = bh >> 4, h = bh & 15;
    const int qrow0 = blockIdx.x * 128 + w * 16;

    const float* kbase = qkv + (size_t)b * NSEQ * (3 * CDIM) + CDIM     + h * HDIM;
    const float* vbase = qkv + (size_t)b * NSEQ * (3 * CDIM) + 2 * CDIM + h * HDIM;

    uint32_t qa[8][4];
    {
        const float* q0 = qkv + (size_t)(b * NSEQ + qrow0) * (3 * CDIM) + h * HDIM;
        #pragma unroll
        for (int kk = 0; kk < 8; ++kk) {
            qa[kk][0] = to_tf32u(q0[(size_t)lr * (3*CDIM)       + kk*8 + lc]     * 0.125f);
            qa[kk][1] = to_tf32u(q0[(size_t)(lr+8) * (3*CDIM)   + kk*8 + lc]     * 0.125f);
            qa[kk][2] = to_tf32u(q0[(size_t)lr * (3*CDIM)       + kk*8 + lc + 4] * 0.125f);
            qa[kk][3] = to_tf32u(q0[(size_t)(lr+8) * (3*CDIM)   + kk*8 + lc + 4] * 0.125f);
        }
    }

    float o[8][4];
    #pragma unroll
    for (int i = 0; i < 8; ++i) { o[i][0]=0.f; o[i][1]=0.f; o[i][2]=0.f; o[i][3]=0.f; }
    float m0 = -1e30f, m1 = -1e30f, l0 = 0.f, l1 = 0.f;

    #pragma unroll
    for (int i = 0; i < 4; ++i) {
        int u = i * 256 + t;
        int r = u >> 4, seg = u & 15;
        cp16(smem_u32(Ks + r * KPAD + seg * 4), kbase + (size_t)r * (3*CDIM) + seg * 4);
        cp16(smem_u32(Vs + r * VPAD + seg * 4), vbase + (size_t)r * (3*CDIM) + seg * 4);
    }
    asm volatile("cp.async.commit_group;" ::: "memory");

    const int NCH = NSEQ / KCH;   // 32
    for (int c = 0; c < NCH; ++c) {
        int buf = c & 1;
        if (c + 1 < NCH) {
            int nb = (c + 1) & 1;
            #pragma unroll
            for (int i = 0; i < 4; ++i) {
                int u = i * 256 + t;
                int r = u >> 4, seg = u & 15;
                const float* ksrc = kbase + (size_t)((c+1) * KCH + r) * (3*CDIM) + seg * 4;
                const float* vsrc = vbase + (size_t)((c+1) * KCH + r) * (3*CDIM) + seg * 4;
                cp16(smem_u32(Ks + nb * KCH * KPAD + r * KPAD + seg * 4), ksrc);
                cp16(smem_u32(Vs + nb * KCH * VPAD + r * VPAD + seg * 4), vsrc);
            }
            asm volatile("cp.async.commit_group;" ::: "memory");
            asm volatile("cp.async.wait_group 1;" ::: "memory");
        } else {
            asm volatile("cp.async.wait_group 0;" ::: "memory");
        }
        __syncthreads();

        const float* Kb = Ks + buf * KCH * KPAD;
        const float* Vb = Vs + buf * KCH * VPAD;

        float s[8][4];
        #pragma unroll
        for (int nj = 0; nj < 8; ++nj) { s[nj][0]=0.f; s[nj][1]=0.f; s[nj][2]=0.f; s[nj][3]=0.f; }
        #pragma unroll
        for (int nj = 0; nj < 8; ++nj) {
            #pragma unroll
            for (int kk = 0; kk < 8; ++kk) {
                uint32_t bf[2];
                bf[0] = __float_as_uint(Kb[(nj*8 + lr) * KPAD + kk*8 + lc]);
                bf[1] = __float_as_uint(Kb[(nj*8 + lr) * KPAD + kk*8 + lc + 4]);
                mma1688(s[nj], qa[kk], bf);
            }
        }

        float rmax0 = -1e30f, rmax1 = -1e30f;
        #pragma unroll
        for (int nj = 0; nj < 8; ++nj) {
            rmax0 = fmaxf(rmax0, fmaxf(s[nj][0], s[nj][1]));
            rmax1 = fmaxf(rmax1, fmaxf(s[nj][2], s[nj][3]));
        }
        rmax0 = fmaxf(rmax0, __shfl_xor_sync(0xffffffffu, rmax0, 1));
        rmax0 = fmaxf(rmax0, __shfl_xor_sync(0xffffffffu, rmax0, 2));
        rmax1 = fmaxf(rmax1, __shfl_xor_sync(0xffffffffu, rmax1, 1));
        rmax1 = fmaxf(rmax1, __shfl_xor_sync(0xffffffffu, rmax1, 2));
        float mn0 = fmaxf(m0, rmax0), mn1 = fmaxf(m1, rmax1);
        float corr0 = __expf(m0 - mn0), corr1 = __expf(m1 - mn1);
        m0 = mn0; m1 = mn1;

        float ls0 = 0.f, ls1 = 0.f;
        #pragma unroll
        for (int nj = 0; nj < 8; ++nj) {
            s[nj][0] = __expf(s[nj][0] - mn0);
            s[nj][1] = __expf(s[nj][1] - mn0);
            s[nj][2] = __expf(s[nj][2] - mn1);
            s[nj][3] = __expf(s[nj][3] - mn1);
            ls0 += s[nj][0] + s[nj][1];
            ls1 += s[nj][2] + s[nj][3];
        }
        ls0 += __shfl_xor_sync(0xffffffffu, ls0, 1);
        ls0 += __shfl_xor_sync(0xffffffffu, ls0, 2);
        ls1 += __shfl_xor_sync(0xffffffffu, ls1, 1);
        ls1 += __shfl_xor_sync(0xffffffffu, ls1, 2);
        l0 = l0 * corr0 + ls0;
        l1 = l1 * corr1 + ls1;

        #pragma unroll
        for (int nj = 0; nj < 8; ++nj) {
            o[nj][0] *= corr0; o[nj][1] *= corr0;
            o[nj][2] *= corr1; o[nj][3] *= corr1;
        }

        #pragma unroll
        for (int kk2 = 0; kk2 < 8; ++kk2) {
            int sl = lr * 4 + (lc >> 1);
            float v00 = __shfl_sync(0xffffffffu, s[kk2][0], sl);
            float v01 = __shfl_sync(0xffffffffu, s[kk2][1], sl);
            float v20 = __shfl_sync(0xffffffffu, s[kk2][2], sl);
            float v21 = __shfl_sync(0xffffffffu, s[kk2][3], sl);
            float w00 = __shfl_sync(0xffffffffu, s[kk2][0], sl + 2);
            float w01 = __shfl_sync(0xffffffffu, s[kk2][1], sl + 2);
            float w20 = __shfl_sync(0xffffffffu, s[kk2][2], sl + 2);
            float w21 = __shfl_sync(0xffffffffu, s[kk2][3], sl + 2);
            uint32_t pa[4];
            bool odd = (lc & 1);
            pa[0] = to_tf32u(odd ? v01 : v00);
            pa[1] = to_tf32u(odd ? v21 : v20);
            pa[2] = to_tf32u(odd ? w01 : w00);
            pa[3] = to_tf32u(odd ? w21 : w20);
            #pragma unroll
            for (int nj2 = 0; nj2 < 8; ++nj2) {
                uint32_t bf[2];
                bf[0] = __float_as_uint(Vb[(kk2*8 + lc) * VPAD + nj2*8 + lr]);
                bf[1] = __float_as_uint(Vb[(kk2*8 + lc + 4) * VPAD + nj2*8 + lr]);
                mma1688(o[nj2], pa, bf);
            }
        }
        __syncthreads();
    }

    float inv0 = 1.0f / l0, inv1 = 1.0f / l1;
    size_t row = (size_t)(b * NSEQ + qrow0 + lr);
    #pragma unroll
    for (int nj2 = 0; nj2 < 8; ++nj2) {
        int col = h * HDIM + nj2 * 8 + 2 * lc;
        __half2 h0 = __floats2half2_rn(o[nj2][0] * inv0, o[nj2][1] * inv0);
        __half2 h1 = __floats2half2_rn(o[nj2][2] * inv1, o[nj2][3] * inv1);
        *(__half2*)&o_out[row * CDIM + col]       = h0;
        *(__half2*)&o_out[(row + 8) * CDIM + col] = h1;
    }
}

// ---------------- host launch ----------------
extern "C" void kernel_launch(void* const* d_in, const int* in_sizes, int n_in,
                              void* d_out, int out_size) {
    const float* x      = (const float*)d_in[0];
    const float* ln1_g  = (const float*)d_in[1];
    const float* ln1_b  = (const float*)d_in[2];
    const float* w_qkv  = (const float*)d_in[3];
    const float* w_proj = (const float*)d_in[4];
    const float* b_proj = (const float*)d_in[5];
    const float* ln2_g  = (const float*)d_in[6];
    const float* ln2_b  = (const float*)d_in[7];
    const float* w_fc1  = (const float*)d_in[8];
    const float* b_fc1  = (const float*)d_in[9];
    const float* w_fc2  = (const float*)d_in[10];
    const float* b_fc2  = (const float*)d_in[11];
    float* out = (float*)d_out;

    __half *h, *o, *h2, *ff, *wqkvT, *wprojT, *wfc1T, *wfc2T;
    float *qkv, *x1;
    cudaGetSymbolAddress((void**)&h,      g_h);
    cudaGetSymbolAddress((void**)&qkv,    g_qkv);
    cudaGetSymbolAddress((void**)&o,      g_o);
    cudaGetSymbolAddress((void**)&x1,     g_x1);
    cudaGetSymbolAddress((void**)&h2,     g_h2);
    cudaGetSymbolAddress((void**)&ff,     g_ff);
    cudaGetSymbolAddress((void**)&wqkvT,  g_wqkvT);
    cudaGetSymbolAddress((void**)&wprojT, g_wprojT);
    cudaGetSymbolAddress((void**)&wfc1T,  g_wfc1T);
    cudaGetSymbolAddress((void**)&wfc2T,  g_wfc2T);

    cudaFuncSetAttribute(gemm_h<0>, cudaFuncAttributeMaxDynamicSharedMemorySize, GEMM_SMEM);
    cudaFuncSetAttribute(gemm_h<1>, cudaFuncAttributeMaxDynamicSharedMemorySize, GEMM_SMEM);
    cudaFuncSetAttribute(gemm_h<2>, cudaFuncAttributeMaxDynamicSharedMemorySize, GEMM_SMEM);
    cudaFuncSetAttribute(attn_mma,  cudaFuncAttributeMaxDynamicSharedMemorySize, AT_SMEM);

    dim3 tb(32, 8);
    transpose_k<<<dim3(3 * CDIM / 32, CDIM / 32), tb>>>(w_qkv, wqkvT, CDIM, 3 * CDIM);
    transpose_k<<<dim3(CDIM / 32, CDIM / 32), tb>>>(w_proj, wprojT, CDIM, CDIM);
    transpose_k<<<dim3(FFDIM / 32, CDIM / 32), tb>>>(w_fc1, wfc1T, CDIM, FFDIM);
    transpose_k<<<dim3(CDIM / 32, FFDIM / 32), tb>>>(w_fc2, wfc2T, FFDIM, CDIM);

    // 1. LN1 (fp16 out)
    ln_kernel<<<M_ROWS, 256>>>(x, ln1_g, ln1_b, h);
    // 2. qkv = h @ w_qkv (fp32 out for attention)
    gemm_h<0><<<dim3(3 * CDIM / 128, M_ROWS / 128), 256, GEMM_SMEM>>>(
        h, wqkvT, nullptr, nullptr, qkv, 3 * CDIM, CDIM);
    // 3. attention (tf32 core, fp16 out)
    attn_mma<<<dim3(NSEQ / 128, 2 * NHEAD), 256, AT_SMEM>>>(qkv, o);
    // 4. x1 = x + o @ w_proj + b_proj (fp32)
    gemm_h<1><<<dim3(CDIM / 128, M_ROWS / 128), 256, GEMM_SMEM>>>(
        o, wprojT, b_proj, x, x1, CDIM, CDIM);
    // 5. LN2 (fp16 out)
    ln_kernel<<<M_ROWS, 256>>>(x1, ln2_g, ln2_b, h2);
    // 6. ff = fp16(gelu(h2 @ w_fc1 + b_fc1))
    gemm_h<2><<<dim3(FFDIM / 128, M_ROWS / 128), 256, GEMM_SMEM>>>(
        h2, wfc1T, b_fc1, nullptr, ff, FFDIM, CDIM);
    // 7. out = x1 + ff @ w_fc2 + b_fc2 (fp32)
    gemm_h<1><<<dim3(CDIM / 128, M_ROWS / 128), 256, GEMM_SMEM>>>(
        ff, wfc2T, b_fc2, x1, out, CDIM, FFDIM);
}

// round 7
// speedup vs baseline: 5.1480x; 1.0117x over previous
#include <cuda_runtime.h>
#include <cuda_fp16.h>
#include <math.h>
#include <stdint.h>

#define M_ROWS 4096
#define CDIM   1024
#define FFDIM  4096
#define NSEQ   2048
#define NHEAD  16
#define HDIM   64

// ---------------- scratch (device globals; no allocs allowed) ----------------
__device__ __half g_h  [M_ROWS * CDIM];      // LN1 out (fp16)
__device__ float  g_qkv[M_ROWS * 3 * CDIM];  // fp32 (attention input)
__device__ __half g_o  [M_ROWS * CDIM];      // attn out (fp16)
__device__ float  g_x1 [M_ROWS * CDIM];      // post-attn residual (fp32)
__device__ __half g_h2 [M_ROWS * CDIM];      // LN2 out (fp16)
__device__ __half g_ff [M_ROWS * FFDIM];     // gelu(fc1) (fp16)
__device__ __half g_wqkvT[3 * CDIM * CDIM];
__device__ __half g_wprojT[CDIM * CDIM];
__device__ __half g_wfc1T[FFDIM * CDIM];
__device__ __half g_wfc2T[CDIM * FFDIM];

// ---------------- helpers ----------------
__device__ __forceinline__ uint32_t smem_u32(const void* p) {
    uint32_t a;
    asm("{ .reg .u64 t; cvta.to.shared.u64 t, %1; cvt.u32.u64 %0, t; }" : "=r"(a) : "l"(p));
    return a;
}
__device__ __forceinline__ void cp16(uint32_t s, const void* g) {
    asm volatile("cp.async.cg.shared.global [%0], [%1], 16;" :: "r"(s), "l"(g) : "memory");
}
__device__ __forceinline__ float to_tf32(float v) {
    uint32_t u;
    asm("cvt.rna.tf32.f32 %0, %1;" : "=r"(u) : "f"(v));
    return __uint_as_float(u);
}
__device__ __forceinline__ uint32_t to_tf32u(float v) {
    uint32_t u;
    asm("cvt.rna.tf32.f32 %0, %1;" : "=r"(u) : "f"(v));
    return u;
}
__device__ __forceinline__ void mma1688(float* d, const uint32_t* a, const uint32_t* b) {
    asm volatile(
        "mma.sync.aligned.m16n8k8.row.col.f32.tf32.tf32.f32 "
        "{%0,%1,%2,%3}, {%4,%5,%6,%7}, {%8,%9}, {%0,%1,%2,%3};"
        : "+f"(d[0]), "+f"(d[1]), "+f"(d[2]), "+f"(d[3])
        : "r"(a[0]), "r"(a[1]), "r"(a[2]), "r"(a[3]), "r"(b[0]), "r"(b[1]));
}
__device__ __forceinline__ void mma16816(float* d, const uint32_t* a, const uint32_t* b) {
    asm volatile(
        "mma.sync.aligned.m16n8k16.row.col.f32.f16.f16.f32 "
        "{%0,%1,%2,%3}, {%4,%5,%6,%7}, {%8,%9}, {%0,%1,%2,%3};"
        : "+f"(d[0]), "+f"(d[1]), "+f"(d[2]), "+f"(d[3])
        : "r"(a[0]), "r"(a[1]), "r"(a[2]), "r"(a[3]), "r"(b[0]), "r"(b[1]));
}
__device__ __forceinline__ void ldsm_x4(uint32_t* r, uint32_t addr) {
    asm volatile("ldmatrix.sync.aligned.m8n8.x4.shared.b16 {%0,%1,%2,%3}, [%4];"
                 : "=r"(r[0]), "=r"(r[1]), "=r"(r[2]), "=r"(r[3]) : "r"(addr));
}
__device__ __forceinline__ float gelu_exact(float v) {
    return 0.5f * v * (1.0f + erff(v * 0.70710678118654752f));
}

// ---------------- weight transpose + fp16 convert: in[K,N] -> out[N,K] ------
__global__ void transpose_k(const float* __restrict__ in, __half* __restrict__ out,
                            int K, int N) {
    __shared__ float tile[32][33];
    int tx = threadIdx.x, ty = threadIdx.y;
    int x = blockIdx.x * 32 + tx;
    int y0 = blockIdx.y * 32;
    #pragma unroll
    for (int j = 0; j < 32; j += 8)
        tile[ty + j][tx] = in[(size_t)(y0 + ty + j) * N + x];
    __syncthreads();
    int ox = y0 + tx;
    int oy0 = blockIdx.x * 32;
    #pragma unroll
    for (int j = 0; j < 32; j += 8)
        out[(size_t)(oy0 + ty + j) * K + ox] = __float2half_rn(tile[tx][ty + j]);
}

// ---------------- fp16 m16n8k16 GEMM, ldmatrix + 4-stage single-sync --------
// C[4096, N] = A[4096, K] @ BT[N, K]^T ; A, BT fp16; accum fp32.
// CTA 128x128, 8 warps (2x4), warp 64x32, k-chunk 32.
// MODE 0: fp32 out   MODE 1: fp32 out +bias +res   MODE 2: fp16 out gelu(+bias)
#define PADH 40
#define STAGE_H (2 * 128 * PADH)            // 10240 halfs per stage (A+B)
#define NSTAGE 4
#define GEMM_SMEM (NSTAGE * STAGE_H * 2)    // 81920 bytes

template <int MODE>
__global__ void __launch_bounds__(256)
gemm_h(const __half* __restrict__ A, const __half* __restrict__ BT,
       const float* __restrict__ bias, const float* __restrict__ res,
       void* __restrict__ Cv, int N, int K) {
    extern __shared__ __half smh[];
    const int t = threadIdx.x;
    const int lane = t & 31;
    const int wid = t >> 5;
    const int wm = wid >> 2;          // 0..1
    const int wn = wid & 3;           // 0..3
    const int lr = lane >> 2;         // 0..7
    const int lc = lane & 3;          // 0..3
    const int row0 = blockIdx.y * 128, col0 = blockIdx.x * 128;
    const __half* gA = A + (size_t)row0 * K;
    const __half* gB = BT + (size_t)col0 * K;
    const int NC = K >> 5;            // chunks of 32

    // ldmatrix lane-address components (constant across chunks)
    const int a_row_in_tile = lane & 15;            // 0..15
    const int a_col_off     = (lane >> 4) << 3;     // 0 or 8 halfs
    const int b_row_in_pair = ((lane >> 4) << 3) + (lane & 7); // 0..15
    const int b_col_off     = ((lane >> 3) & 1) << 3;          // 0 or 8 halfs

    float d[4][4][4];
    #pragma unroll
    for (int i = 0; i < 4; ++i)
        #pragma unroll
        for (int j = 0; j < 4; ++j)
            #pragma unroll
            for (int e = 0; e < 4; ++e) d[i][j][e] = 0.f;

    // prologue: fill stages 0..2 (of 4)
    #pragma unroll
    for (int s = 0; s < 3; ++s) {
        __half* dA = smh + s * STAGE_H;
        __half* dB = dA + 128 * PADH;
        int k0 = s << 5;
        #pragma unroll
        for (int i = 0; i < 2; ++i) {
            int u = i * 256 + t;          // 0..511
            int r = u >> 2, seg = u & 3;
            cp16(smem_u32(dA + r * PADH + seg * 8), gA + (size_t)r * K + k0 + seg * 8);
            cp16(smem_u32(dB + r * PADH + seg * 8), gB + (size_t)r * K + k0 + seg * 8);
        }
        asm volatile("cp.async.commit_group;" ::: "memory");
    }

    for (int c = 0; c < NC; ++c) {
        int b = c & 3;
        asm volatile("cp.async.wait_group 2;" ::: "memory");
        __syncthreads();
        // buffer (c+3)%4 == (c-1)%4 is free (all warps finished chunk c-1)
        if (c + 3 < NC) {
            int nb = (c + 3) & 3;
            __half* dA = smh + nb * STAGE_H;
            __half* dB = dA + 128 * PADH;
            int k0 = (c + 3) << 5;
            #pragma unroll
            for (int i = 0; i < 2; ++i) {
                int u = i * 256 + t;
                int r = u >> 2, seg = u & 3;
                cp16(smem_u32(dA + r * PADH + seg * 8), gA + (size_t)r * K + k0 + seg * 8);
                cp16(smem_u32(dB + r * PADH + seg * 8), gB + (size_t)r * K + k0 + seg * 8);
            }
        }
        asm volatile("cp.async.commit_group;" ::: "memory");

        const __half* As = smh + b * STAGE_H;
        const __half* Bs = As + 128 * PADH;
        #pragma unroll
        for (int s = 0; s < 2; ++s) {           // two k16 steps
            uint32_t af[4][4], bf2[2][4];
            #pragma unroll
            for (int mi = 0; mi < 4; ++mi) {
                uint32_t addr = smem_u32(As + (wm * 64 + mi * 16 + a_row_in_tile) * PADH
                                            + s * 16 + a_col_off);
                ldsm_x4(af[mi], addr);
            }
            #pragma unroll
            for (int njp = 0; njp < 2; ++njp) {
                uint32_t addr = smem_u32(Bs + (wn * 32 + njp * 16 + b_row_in_pair) * PADH
                                            + s * 16 + b_col_off);
                ldsm_x4(bf2[njp], addr);
            }
            #pragma unroll
            for (int mi = 0; mi < 4; ++mi) {
                #pragma unroll
                for (int nj = 0; nj < 4; ++nj) {
                    const uint32_t* bf = &bf2[nj >> 1][(nj & 1) << 1];
                    mma16816(d[mi][nj], af[mi], bf);
                }
            }
        }
        // no second sync: next iteration's barrier protects buffer reuse
    }

    // epilogue
    #pragma unroll
    for (int mi = 0; mi < 4; ++mi) {
        #pragma unroll
        for (int nj = 0; nj < 4; ++nj) {
            int row = row0 + wm * 64 + mi * 16 + lr;
            int col = col0 + wn * 32 + nj * 8 + 2 * lc;
            float2 v0 = make_float2(d[mi][nj][0], d[mi][nj][1]);
            float2 v1 = make_float2(d[mi][nj][2], d[mi][nj][3]);
            if (MODE >= 1) {
                float2 bv = *(const float2*)&bias[col];
                v0.x += bv.x; v0.y += bv.y;
                v1.x += bv.x; v1.y += bv.y;
            }
            if (MODE == 1) {
                float* Cf = (float*)Cv;
                float2 r0 = *(const float2*)&res[(size_t)row * N + col];
                float2 r1 = *(const float2*)&res[(size_t)(row + 8) * N + col];
                v0.x += r0.x; v0.y += r0.y;
                v1.x += r1.x; v1.y += r1.y;
                *(float2*)&Cf[(size_t)row * N + col]       = v0;
                *(float2*)&Cf[(size_t)(row + 8) * N + col] = v1;
            } else if (MODE == 2) {
                __half* Ch = (__half*)Cv;
                __half2 h0 = __floats2half2_rn(gelu_exact(v0.x), gelu_exact(v0.y));
                __half2 h1 = __floats2half2_rn(gelu_exact(v1.x), gelu_exact(v1.y));
                *(__half2*)&Ch[(size_t)row * N + col]       = h0;
                *(__half2*)&Ch[(size_t)(row + 8) * N + col] = h1;
            } else {
                float* Cf = (float*)Cv;
                *(float2*)&Cf[(size_t)row * N + col]       = v0;
                *(float2*)&Cf[(size_t)(row + 8) * N + col] = v1;
            }
        }
    }
}

// ---------------- LayerNorm (fp16 output: feeds GEMM A) ----------------
__global__ void ln_kernel(const float* __restrict__ x,
                          const float* __restrict__ g,
                          const float* __restrict__ b,
                          __half* __restrict__ y) {
    int row = blockIdx.x;
    int t = threadIdx.x;
    const float4* xr = (const float4*)(x + (size_t)row * CDIM);
    float4 v = xr[t];
    float s  = v.x + v.y + v.z + v.w;
    float ss = v.x*v.x + v.y*v.y + v.z*v.z + v.w*v.w;
    #pragma unroll
    for (int off = 16; off > 0; off >>= 1) {
        s  += __shfl_xor_sync(0xffffffffu, s,  off);
        ss += __shfl_xor_sync(0xffffffffu, ss, off);
    }
    __shared__ float sbuf[8], ssbuf[8];
    int warp = t >> 5, lane = t & 31;
    if (lane == 0) { sbuf[warp] = s; ssbuf[warp] = ss; }
    __syncthreads();
    float tot = 0.f, tot2 = 0.f;
    #pragma unroll
    for (int w = 0; w < 8; ++w) { tot += sbuf[w]; tot2 += ssbuf[w]; }
    float mean = tot * (1.0f / CDIM);
    float var  = tot2 * (1.0f / CDIM) - mean * mean;
    float rstd = rsqrtf(var + 1e-5f);
    float4 gg = ((const float4*)g)[t];
    float4 bb = ((const float4*)b)[t];
    __half2 h0 = __floats2half2_rn((v.x - mean) * rstd * gg.x + bb.x,
                                   (v.y - mean) * rstd * gg.y + bb.y);
    __half2 h1 = __floats2half2_rn((v.z - mean) * rstd * gg.z + bb.z,
                                   (v.w - mean) * rstd * gg.w + bb.w);
    __half2* yp = (__half2*)(y + (size_t)row * CDIM + t * 4);
    yp[0] = h0;
    yp[1] = h1;
}

// ---------------- Tensor-core flash attention (tf32, unchanged) -------------
#define KCH  64
#define KPAD 68
#define VPAD 72
#define AT_SMEM ((2 * KCH * KPAD + 2 * KCH * VPAD) * 4)

__global__ void __launch_bounds__(256)
attn_mma(const float* __restrict__ qkv, __half* __restrict__ o_out) {
    extern __shared__ float as_[];
    float* Ks = as_;                         // [2][64][KPAD]
    float* Vs = as_ + 2 * KCH * KPAD;        // [2][64][VPAD]

    const int t = threadIdx.x, lane = t & 31, w = t >> 5;
    const int lr = lane >> 2, lc = lane & 3;
    const int bh = blockIdx.y, b = bh >> 4, h = bh & 15;
    const int qrow0 = blockIdx.x * 128 + w * 16;

    const float* kbase = qkv + (size_t)b * NSEQ * (3 * CDIM) + CDIM     + h * HDIM;
    const float* vbase = qkv + (size_t)b * NSEQ * (3 * CDIM) + 2 * CDIM + h * HDIM;

    uint32_t qa[8][4];
    {
        const float* q0 = qkv + (size_t)(b * NSEQ + qrow0) * (3 * CDIM) + h * HDIM;
        #pragma unroll
        for (int kk = 0; kk < 8; ++kk) {
            qa[kk][0] = to_tf32u(q0[(size_t)lr * (3*CDIM)       + kk*8 + lc]     * 0.125f);
            qa[kk][1] = to_tf32u(q0[(size_t)(lr+8) * (3*CDIM)   + kk*8 + lc]     * 0.125f);
            qa[kk][2] = to_tf32u(q0[(size_t)lr * (3*CDIM)       + kk*8 + lc + 4] * 0.125f);
            qa[kk][3] = to_tf32u(q0[(size_t)(lr+8) * (3*CDIM)   + kk*8 + lc + 4] * 0.125f);
        }
    }

    float o[8][4];
    #pragma unroll
    for (int i = 0; i < 8; ++i) { o[i][0]=0.f; o[i][1]=0.f; o[i][2]=0.f; o[i][3]=0.f; }
    float m0 = -1e30f, m1 = -1e30f, l0 = 0.f, l1 = 0.f;

    #pragma unroll
    for (int i = 0; i < 4; ++i) {
        int u = i * 256 + t;
        int r = u >> 4, seg = u & 15;
        cp16(smem_u32(Ks + r * KPAD + seg * 4), kbase + (size_t)r * (3*CDIM) + seg * 4);
        cp16(smem_u32(Vs + r * VPAD + seg * 4), vbase + (size_t)r * (3*CDIM) + seg * 4);
    }
    asm volatile("cp.async.commit_group;" ::: "memory");

    const int NCH = NSEQ / KCH;   // 32
    for (int c = 0; c < NCH; ++c) {
        int buf = c & 1;
        if (c + 1 < NCH) {
            int nb = (c + 1) & 1;
            #pragma unroll
            for (int i = 0; i < 4; ++i) {
                int u = i * 256 + t;
                int r = u >> 4, seg = u & 15;
                const float* ksrc = kbase + (size_t)((c+1) * KCH + r) * (3*CDIM) + seg * 4;
                const float* vsrc = vbase + (size_t)((c+1) * KCH + r) * (3*CDIM) + seg * 4;
                cp16(smem_u32(Ks + nb * KCH * KPAD + r * KPAD + seg * 4), ksrc);
                cp16(smem_u32(Vs + nb * KCH * VPAD + r * VPAD + seg * 4), vsrc);
            }
            asm volatile("cp.async.commit_group;" ::: "memory");
            asm volatile("cp.async.wait_group 1;" ::: "memory");
        } else {
            asm volatile("cp.async.wait_group 0;" ::: "memory");
        }
        __syncthreads();

        const float* Kb = Ks + buf * KCH * KPAD;
        const float* Vb = Vs + buf * KCH * VPAD;

        float s[8][4];
        #pragma unroll
        for (int nj = 0; nj < 8; ++nj) { s[nj][0]=0.f; s[nj][1]=0.f; s[nj][2]=0.f; s[nj][3]=0.f; }
        #pragma unroll
        for (int nj = 0; nj < 8; ++nj) {
            #pragma unroll
            for (int kk = 0; kk < 8; ++kk) {
                uint32_t bf[2];
                bf[0] = __float_as_uint(Kb[(nj*8 + lr) * KPAD + kk*8 + lc]);
                bf[1] = __float_as_uint(Kb[(nj*8 + lr) * KPAD + kk*8 + lc + 4]);
                mma1688(s[nj], qa[kk], bf);
            }
        }

        float rmax0 = -1e30f, rmax1 = -1e30f;
        #pragma unroll
        for (int nj = 0; nj < 8; ++nj) {
            rmax0 = fmaxf(rmax0, fmaxf(s[nj][0], s[nj][1]));
            rmax1 = fmaxf(rmax1, fmaxf(s[nj][2], s[nj][3]));
        }
        rmax0 = fmaxf(rmax0, __shfl_xor_sync(0xffffffffu, rmax0, 1));
        rmax0 = fmaxf(rmax0, __shfl_xor_sync(0xffffffffu, rmax0, 2));
        rmax1 = fmaxf(rmax1, __shfl_xor_sync(0xffffffffu, rmax1, 1));
        rmax1 = fmaxf(rmax1, __shfl_xor_sync(0xffffffffu, rmax1, 2));
        float mn0 = fmaxf(m0, rmax0), mn1 = fmaxf(m1, rmax1);
        float corr0 = __expf(m0 - mn0), corr1 = __expf(m1 - mn1);
        m0 = mn0; m1 = mn1;

        float ls0 = 0.f, ls1 = 0.f;
        #pragma unroll
        for (int nj = 0; nj < 8; ++nj) {
            s[nj][0] = __expf(s[nj][0] - mn0);
            s[nj][1] = __expf(s[nj][1] - mn0);
            s[nj][2] = __expf(s[nj][2] - mn1);
            s[nj][3] = __expf(s[nj][3] - mn1);
            ls0 += s[nj][0] + s[nj][1];
            ls1 += s[nj][2] + s[nj][3];
        }
        ls0 += __shfl_xor_sync(0xffffffffu, ls0, 1);
        ls0 += __shfl_xor_sync(0xffffffffu, ls0, 2);
        ls1 += __shfl_xor_sync(0xffffffffu, ls1, 1);
        ls1 += __shfl_xor_sync(0xffffffffu, ls1, 2);
        l0 = l0 * corr0 + ls0;
        l1 = l1 * corr1 + ls1;

        #pragma unroll
        for (int nj = 0; nj < 8; ++nj) {
            o[nj][0] *= corr0; o[nj][1] *= corr0;
            o[nj][2] *= corr1; o[nj][3] *= corr1;
        }

        #pragma unroll
        for (int kk2 = 0; kk2 < 8; ++kk2) {
            int sl = lr * 4 + (lc >> 1);
            float v00 = __shfl_sync(0xffffffffu, s[kk2][0], sl);
            float v01 = __shfl_sync(0xffffffffu, s[kk2][1], sl);
            float v20 = __shfl_sync(0xffffffffu, s[kk2][2], sl);
            float v21 = __shfl_sync(0xffffffffu, s[kk2][3], sl);
            float w00 = __shfl_sync(0xffffffffu, s[kk2][0], sl + 2);
            float w01 = __shfl_sync(0xffffffffu, s[kk2][1], sl + 2);
            float w20 = __shfl_sync(0xffffffffu, s[kk2][2], sl + 2);
            float w21 = __shfl_sync(0xffffffffu, s[kk2][3], sl + 2);
            uint32_t pa[4];
            bool odd = (lc & 1);
            pa[0] = to_tf32u(odd ? v01 : v00);
            pa[1] = to_tf32u(odd ? v21 : v20);
            pa[2] = to_tf32u(odd ? w01 : w00);
            pa[3] = to_tf32u(odd ? w21 : w20);
            #pragma unroll
            for (int nj2 = 0; nj2 < 8; ++nj2) {
                uint32_t bf[2];
                bf[0] = __float_as_uint(Vb[(kk2*8 + lc) * VPAD + nj2*8 + lr]);
                bf[1] = __float_as_uint(Vb[(kk2*8 + lc + 4) * VPAD + nj2*8 + lr]);
                mma1688(o[nj2], pa, bf);
            }
        }
        __syncthreads();
    }

    float inv0 = 1.0f / l0, inv1 = 1.0f / l1;
    size_t row = (size_t)(b * NSEQ + qrow0 + lr);
    #pragma unroll
    for (int nj2 = 0; nj2 < 8; ++nj2) {
        int col = h * HDIM + nj2 * 8 + 2 * lc;
        __half2 h0 = __floats2half2_rn(o[nj2][0] * inv0, o[nj2][1] * inv0);
        __half2 h1 = __floats2half2_rn(o[nj2][2] * inv1, o[nj2][3] * inv1);
        *(__half2*)&o_out[row * CDIM + col]       = h0;
        *(__half2*)&o_out[(row + 8) * CDIM + col] = h1;
    }
}

// ---------------- host launch ----------------
extern "C" void kernel_launch(void* const* d_in, const int* in_sizes, int n_in,
                              void* d_out, int out_size) {
    const float* x      = (const float*)d_in[0];
    const float* ln1_g  = (const float*)d_in[1];
    const float* ln1_b  = (const float*)d_in[2];
    const float* w_qkv  = (const float*)d_in[3];
    const float* w_proj = (const float*)d_in[4];
    const float* b_proj = (const float*)d_in[5];
    const float* ln2_g  = (const float*)d_in[6];
    const float* ln2_b  = (const float*)d_in[7];
    const float* w_fc1  = (const float*)d_in[8];
    const float* b_fc1  = (const float*)d_in[9];
    const float* w_fc2  = (const float*)d_in[10];
    const float* b_fc2  = (const float*)d_in[11];
    float* out = (float*)d_out;

    __half *h, *o, *h2, *ff, *wqkvT, *wprojT, *wfc1T, *wfc2T;
    float *qkv, *x1;
    cudaGetSymbolAddress((void**)&h,      g_h);
    cudaGetSymbolAddress((void**)&qkv,    g_qkv);
    cudaGetSymbolAddress((void**)&o,      g_o);
    cudaGetSymbolAddress((void**)&x1,     g_x1);
    cudaGetSymbolAddress((void**)&h2,     g_h2);
    cudaGetSymbolAddress((void**)&ff,     g_ff);
    cudaGetSymbolAddress((void**)&wqkvT,  g_wqkvT);
    cudaGetSymbolAddress((void**)&wprojT, g_wprojT);
    cudaGetSymbolAddress((void**)&wfc1T,  g_wfc1T);
    cudaGetSymbolAddress((void**)&wfc2T,  g_wfc2T);

    cudaFuncSetAttribute(gemm_h<0>, cudaFuncAttributeMaxDynamicSharedMemorySize, GEMM_SMEM);
    cudaFuncSetAttribute(gemm_h<1>, cudaFuncAttributeMaxDynamicSharedMemorySize, GEMM_SMEM);
    cudaFuncSetAttribute(gemm_h<2>, cudaFuncAttributeMaxDynamicSharedMemorySize, GEMM_SMEM);
    cudaFuncSetAttribute(attn_mma,  cudaFuncAttributeMaxDynamicSharedMemorySize, AT_SMEM);

    dim3 tb(32, 8);
    transpose_k<<<dim3(3 * CDIM / 32, CDIM / 32), tb>>>(w_qkv, wqkvT, CDIM, 3 * CDIM);
    transpose_k<<<dim3(CDIM / 32, CDIM / 32), tb>>>(w_proj, wprojT, CDIM, CDIM);
    transpose_k<<<dim3(FFDIM / 32, CDIM / 32), tb>>>(w_fc1, wfc1T, CDIM, FFDIM);
    transpose_k<<<dim3(CDIM / 32, FFDIM / 32), tb>>>(w_fc2, wfc2T, FFDIM, CDIM);

    // 1. LN1 (fp16 out)
    ln_kernel<<<M_ROWS, 256>>>(x, ln1_g, ln1_b, h);
    // 2. qkv = h @ w_qkv (fp32 out for attention)
    gemm_h<0><<<dim3(3 * CDIM / 128, M_ROWS / 128), 256, GEMM_SMEM>>>(
        h, wqkvT, nullptr, nullptr, qkv, 3 * CDIM, CDIM);
    // 3. attention (tf32 core, fp16 out)
    attn_mma<<<dim3(NSEQ / 128, 2 * NHEAD), 256, AT_SMEM>>>(qkv, o);
    // 4. x1 = x + o @ w_proj + b_proj (fp32)
    gemm_h<1><<<dim3(CDIM / 128, M_ROWS / 128), 256, GEMM_SMEM>>>(
        o, wprojT, b_proj, x, x1, CDIM, CDIM);
    // 5. LN2 (fp16 out)
    ln_kernel<<<M_ROWS, 256>>>(x1, ln2_g, ln2_b, h2);
    // 6. ff = fp16(gelu(h2 @ w_fc1 + b_fc1))
    gemm_h<2><<<dim3(FFDIM / 128, M_ROWS / 128), 256, GEMM_SMEM>>>(
        h2, wfc1T, b_fc1, nullptr, ff, FFDIM, CDIM);
    // 7. out = x1 + ff @ w_fc2 + b_fc2 (fp32)
    gemm_h<1><<<dim3(CDIM / 128, M_ROWS / 128), 256, GEMM_SMEM>>>(
        ff, wfc2T, b_fc2, x1, out, CDIM, FFDIM);
}

// round 8
// speedup vs baseline: 6.2481x; 1.2137x over previous
#include <cuda_runtime.h>
#include <cuda_fp16.h>
#include <math.h>
#include <stdint.h>

#define M_ROWS 4096
#define CDIM   1024
#define FFDIM  4096
#define NSEQ   2048
#define NHEAD  16
#define HDIM   64

// ---------------- scratch (device globals; no allocs allowed) ----------------
__device__ __half g_h  [M_ROWS * CDIM];      // LN1 out (fp16)
__device__ __half g_qkv[M_ROWS * 3 * CDIM];  // fp16 qkv (attention input)
__device__ __half g_o  [M_ROWS * CDIM];      // attn out (fp16)
__device__ float  g_x1 [M_ROWS * CDIM];      // post-attn residual (fp32)
__device__ __half g_h2 [M_ROWS * CDIM];      // LN2 out (fp16)
__device__ __half g_ff [M_ROWS * FFDIM];     // gelu(fc1) (fp16)
__device__ __half g_wqkvT[3 * CDIM * CDIM];
__device__ __half g_wprojT[CDIM * CDIM];
__device__ __half g_wfc1T[FFDIM * CDIM];
__device__ __half g_wfc2T[CDIM * FFDIM];

// ---------------- helpers ----------------
__device__ __forceinline__ uint32_t smem_u32(const void* p) {
    uint32_t a;
    asm("{ .reg .u64 t; cvta.to.shared.u64 t, %1; cvt.u32.u64 %0, t; }" : "=r"(a) : "l"(p));
    return a;
}
__device__ __forceinline__ void cp16(uint32_t s, const void* g) {
    asm volatile("cp.async.cg.shared.global [%0], [%1], 16;" :: "r"(s), "l"(g) : "memory");
}
__device__ __forceinline__ void mma16816(float* d, const uint32_t* a, const uint32_t* b) {
    asm volatile(
        "mma.sync.aligned.m16n8k16.row.col.f32.f16.f16.f32 "
        "{%0,%1,%2,%3}, {%4,%5,%6,%7}, {%8,%9}, {%0,%1,%2,%3};"
        : "+f"(d[0]), "+f"(d[1]), "+f"(d[2]), "+f"(d[3])
        : "r"(a[0]), "r"(a[1]), "r"(a[2]), "r"(a[3]), "r"(b[0]), "r"(b[1]));
}
__device__ __forceinline__ void ldsm_x4(uint32_t* r, uint32_t addr) {
    asm volatile("ldmatrix.sync.aligned.m8n8.x4.shared.b16 {%0,%1,%2,%3}, [%4];"
                 : "=r"(r[0]), "=r"(r[1]), "=r"(r[2]), "=r"(r[3]) : "r"(addr));
}
__device__ __forceinline__ void ldsm_x4_t(uint32_t* r, uint32_t addr) {
    asm volatile("ldmatrix.sync.aligned.m8n8.x4.trans.shared.b16 {%0,%1,%2,%3}, [%4];"
                 : "=r"(r[0]), "=r"(r[1]), "=r"(r[2]), "=r"(r[3]) : "r"(addr));
}
__device__ __forceinline__ uint32_t packh2(float a, float b) {
    __half2 h = __floats2half2_rn(a, b);
    return *(uint32_t*)&h;
}
__device__ __forceinline__ float gelu_exact(float v) {
    return 0.5f * v * (1.0f + erff(v * 0.70710678118654752f));
}

// ---------------- weight transpose + fp16 convert: in[K,N] -> out[N,K] ------
__global__ void transpose_k(const float* __restrict__ in, __half* __restrict__ out,
                            int K, int N) {
    __shared__ float tile[32][33];
    int tx = threadIdx.x, ty = threadIdx.y;
    int x = blockIdx.x * 32 + tx;
    int y0 = blockIdx.y * 32;
    #pragma unroll
    for (int j = 0; j < 32; j += 8)
        tile[ty + j][tx] = in[(size_t)(y0 + ty + j) * N + x];
    __syncthreads();
    int ox = y0 + tx;
    int oy0 = blockIdx.x * 32;
    #pragma unroll
    for (int j = 0; j < 32; j += 8)
        out[(size_t)(oy0 + ty + j) * K + ox] = __float2half_rn(tile[tx][ty + j]);
}

// ---------------- fp16 m16n8k16 GEMM (unchanged core from R7) ----------------
// MODE 0: fp16 out   MODE 1: fp32 out +bias +res   MODE 2: fp16 out gelu(+bias)
#define PADH 40
#define STAGE_H (2 * 128 * PADH)
#define NSTAGE 4
#define GEMM_SMEM (NSTAGE * STAGE_H * 2)

template <int MODE>
__global__ void __launch_bounds__(256)
gemm_h(const __half* __restrict__ A, const __half* __restrict__ BT,
       const float* __restrict__ bias, const float* __restrict__ res,
       void* __restrict__ Cv, int N, int K) {
    extern __shared__ __half smh[];
    const int t = threadIdx.x;
    const int lane = t & 31;
    const int wid = t >> 5;
    const int wm = wid >> 2;
    const int wn = wid & 3;
    const int lr = lane >> 2;
    const int lc = lane & 3;
    const int row0 = blockIdx.y * 128, col0 = blockIdx.x * 128;
    const __half* gA = A + (size_t)row0 * K;
    const __half* gB = BT + (size_t)col0 * K;
    const int NC = K >> 5;

    const int a_row_in_tile = lane & 15;
    const int a_col_off     = (lane >> 4) << 3;
    const int b_row_in_pair = ((lane >> 4) << 3) + (lane & 7);
    const int b_col_off     = ((lane >> 3) & 1) << 3;

    float d[4][4][4];
    #pragma unroll
    for (int i = 0; i < 4; ++i)
        #pragma unroll
        for (int j = 0; j < 4; ++j)
            #pragma unroll
            for (int e = 0; e < 4; ++e) d[i][j][e] = 0.f;

    #pragma unroll
    for (int s = 0; s < 3; ++s) {
        __half* dA = smh + s * STAGE_H;
        __half* dB = dA + 128 * PADH;
        int k0 = s << 5;
        #pragma unroll
        for (int i = 0; i < 2; ++i) {
            int u = i * 256 + t;
            int r = u >> 2, seg = u & 3;
            cp16(smem_u32(dA + r * PADH + seg * 8), gA + (size_t)r * K + k0 + seg * 8);
            cp16(smem_u32(dB + r * PADH + seg * 8), gB + (size_t)r * K + k0 + seg * 8);
        }
        asm volatile("cp.async.commit_group;" ::: "memory");
    }

    for (int c = 0; c < NC; ++c) {
        int b = c & 3;
        asm volatile("cp.async.wait_group 2;" ::: "memory");
        __syncthreads();
        if (c + 3 < NC) {
            int nb = (c + 3) & 3;
            __half* dA = smh + nb * STAGE_H;
            __half* dB = dA + 128 * PADH;
            int k0 = (c + 3) << 5;
            #pragma unroll
            for (int i = 0; i < 2; ++i) {
                int u = i * 256 + t;
                int r = u >> 2, seg = u & 3;
                cp16(smem_u32(dA + r * PADH + seg * 8), gA + (size_t)r * K + k0 + seg * 8);
                cp16(smem_u32(dB + r * PADH + seg * 8), gB + (size_t)r * K + k0 + seg * 8);
            }
        }
        asm volatile("cp.async.commit_group;" ::: "memory");

        const __half* As = smh + b * STAGE_H;
        const __half* Bs = As + 128 * PADH;
        #pragma unroll
        for (int s = 0; s < 2; ++s) {
            uint32_t af[4][4], bf2[2][4];
            #pragma unroll
            for (int mi = 0; mi < 4; ++mi) {
                uint32_t addr = smem_u32(As + (wm * 64 + mi * 16 + a_row_in_tile) * PADH
                                            + s * 16 + a_col_off);
                ldsm_x4(af[mi], addr);
            }
            #pragma unroll
            for (int njp = 0; njp < 2; ++njp) {
                uint32_t addr = smem_u32(Bs + (wn * 32 + njp * 16 + b_row_in_pair) * PADH
                                            + s * 16 + b_col_off);
                ldsm_x4(bf2[njp], addr);
            }
            #pragma unroll
            for (int mi = 0; mi < 4; ++mi) {
                #pragma unroll
                for (int nj = 0; nj < 4; ++nj) {
                    const uint32_t* bf = &bf2[nj >> 1][(nj & 1) << 1];
                    mma16816(d[mi][nj], af[mi], bf);
                }
            }
        }
    }

    #pragma unroll
    for (int mi = 0; mi < 4; ++mi) {
        #pragma unroll
        for (int nj = 0; nj < 4; ++nj) {
            int row = row0 + wm * 64 + mi * 16 + lr;
            int col = col0 + wn * 32 + nj * 8 + 2 * lc;
            float2 v0 = make_float2(d[mi][nj][0], d[mi][nj][1]);
            float2 v1 = make_float2(d[mi][nj][2], d[mi][nj][3]);
            if (MODE >= 1) {
                float2 bv = *(const float2*)&bias[col];
                v0.x += bv.x; v0.y += bv.y;
                v1.x += bv.x; v1.y += bv.y;
            }
            if (MODE == 1) {
                float* Cf = (float*)Cv;
                float2 r0 = *(const float2*)&res[(size_t)row * N + col];
                float2 r1 = *(const float2*)&res[(size_t)(row + 8) * N + col];
                v0.x += r0.x; v0.y += r0.y;
                v1.x += r1.x; v1.y += r1.y;
                *(float2*)&Cf[(size_t)row * N + col]       = v0;
                *(float2*)&Cf[(size_t)(row + 8) * N + col] = v1;
            } else if (MODE == 2) {
                __half* Ch = (__half*)Cv;
                __half2 h0 = __floats2half2_rn(gelu_exact(v0.x), gelu_exact(v0.y));
                __half2 h1 = __floats2half2_rn(gelu_exact(v1.x), gelu_exact(v1.y));
                *(__half2*)&Ch[(size_t)row * N + col]       = h0;
                *(__half2*)&Ch[(size_t)(row + 8) * N + col] = h1;
            } else {
                __half* Ch = (__half*)Cv;
                __half2 h0 = __floats2half2_rn(v0.x, v0.y);
                __half2 h1 = __floats2half2_rn(v1.x, v1.y);
                *(__half2*)&Ch[(size_t)row * N + col]       = h0;
                *(__half2*)&Ch[(size_t)(row + 8) * N + col] = h1;
            }
        }
    }
}

// ---------------- LayerNorm (fp16 output) ----------------
__global__ void ln_kernel(const float* __restrict__ x,
                          const float* __restrict__ g,
                          const float* __restrict__ b,
                          __half* __restrict__ y) {
    int row = blockIdx.x;
    int t = threadIdx.x;
    const float4* xr = (const float4*)(x + (size_t)row * CDIM);
    float4 v = xr[t];
    float s  = v.x + v.y + v.z + v.w;
    float ss = v.x*v.x + v.y*v.y + v.z*v.z + v.w*v.w;
    #pragma unroll
    for (int off = 16; off > 0; off >>= 1) {
        s  += __shfl_xor_sync(0xffffffffu, s,  off);
        ss += __shfl_xor_sync(0xffffffffu, ss, off);
    }
    __shared__ float sbuf[8], ssbuf[8];
    int warp = t >> 5, lane = t & 31;
    if (lane == 0) { sbuf[warp] = s; ssbuf[warp] = ss; }
    __syncthreads();
    float tot = 0.f, tot2 = 0.f;
    #pragma unroll
    for (int w = 0; w < 8; ++w) { tot += sbuf[w]; tot2 += ssbuf[w]; }
    float mean = tot * (1.0f / CDIM);
    float var  = tot2 * (1.0f / CDIM) - mean * mean;
    float rstd = rsqrtf(var + 1e-5f);
    float4 gg = ((const float4*)g)[t];
    float4 bb = ((const float4*)b)[t];
    __half2 h0 = __floats2half2_rn((v.x - mean) * rstd * gg.x + bb.x,
                                   (v.y - mean) * rstd * gg.y + bb.y);
    __half2 h1 = __floats2half2_rn((v.z - mean) * rstd * gg.z + bb.z,
                                   (v.w - mean) * rstd * gg.w + bb.w);
    __half2* yp = (__half2*)(y + (size_t)row * CDIM + t * 4);
    yp[0] = h0;
    yp[1] = h1;
}

// ---------------- fp16 tensor-core flash attention ----------------
// Grid (16, 32), 256 threads (8 warps); warp w owns q-rows [w*16, w*16+16).
// KV chunks of 64 rows, double-buffered cp.async; all mma fp16 m16n8k16.
// P re-fragmentation is thread-local (C-layout == A-layout packed to half2).
#define KCH    64
#define KVPADH 72
#define KVT_H  (KCH * KVPADH)                 // halfs per tile
#define AT_SMEM (4 * KVT_H * 2)               // K0,K1,V0,V1 = 36864 bytes

__global__ void __launch_bounds__(256)
attn_mma(const __half* __restrict__ qkv, __half* __restrict__ o_out) {
    extern __shared__ __half ash[];
    __half* Ks = ash;                         // [2][64][KVPADH]
    __half* Vs = ash + 2 * KVT_H;             // [2][64][KVPADH]

    const int t = threadIdx.x, lane = t & 31, w = t >> 5;
    const int lr = lane >> 2, lc = lane & 3;
    const int bh = blockIdx.y, b = bh >> 4, h = bh & 15;
    const int qrow0 = blockIdx.x * 128 + w * 16;

    const __half* kbase = qkv + (size_t)b * NSEQ * (3 * CDIM) + CDIM     + h * HDIM;
    const __half* vbase = qkv + (size_t)b * NSEQ * (3 * CDIM) + 2 * CDIM + h * HDIM;

    // Q fragments (A layout, 4 k16 steps), pre-scaled by D^-1/2
    uint32_t qa[4][4];
    {
        const __half* q0 = qkv + (size_t)(b * NSEQ + qrow0) * (3 * CDIM) + h * HDIM;
        #pragma unroll
        for (int kk = 0; kk < 4; ++kk) {
            #pragma unroll
            for (int e = 0; e < 4; ++e) {
                int rowo = (e & 1) ? lr + 8 : lr;
                int colo = kk * 16 + 2 * lc + ((e & 2) ? 8 : 0);
                __half2 hv = *(const __half2*)&q0[(size_t)rowo * (3 * CDIM) + colo];
                float2 fv = __half22float2(hv);
                qa[kk][e] = packh2(fv.x * 0.125f, fv.y * 0.125f);
            }
        }
    }

    float o[8][4];
    #pragma unroll
    for (int i = 0; i < 8; ++i) { o[i][0]=0.f; o[i][1]=0.f; o[i][2]=0.f; o[i][3]=0.f; }
    float m0 = -1e30f, m1 = -1e30f, l0 = 0.f, l1 = 0.f;

    // tile load: 64 rows x 8 segments(16B=8 halfs) = 512 units, 2 per thread
    #pragma unroll
    for (int i = 0; i < 2; ++i) {
        int u = i * 256 + t;
        int r = u >> 3, seg = u & 7;
        cp16(smem_u32(Ks + r * KVPADH + seg * 8), kbase + (size_t)r * (3*CDIM) + seg * 8);
        cp16(smem_u32(Vs + r * KVPADH + seg * 8), vbase + (size_t)r * (3*CDIM) + seg * 8);
    }
    asm volatile("cp.async.commit_group;" ::: "memory");

    const int NCH = NSEQ / KCH;   // 32
    for (int c = 0; c < NCH; ++c) {
        int buf = c & 1;
        if (c + 1 < NCH) {
            int nb = (c + 1) & 1;
            #pragma unroll
            for (int i = 0; i < 2; ++i) {
                int u = i * 256 + t;
                int r = u >> 3, seg = u & 7;
                const __half* ksrc = kbase + (size_t)((c+1) * KCH + r) * (3*CDIM) + seg * 8;
                const __half* vsrc = vbase + (size_t)((c+1) * KCH + r) * (3*CDIM) + seg * 8;
                cp16(smem_u32(Ks + nb * KVT_H + r * KVPADH + seg * 8), ksrc);
                cp16(smem_u32(Vs + nb * KVT_H + r * KVPADH + seg * 8), vsrc);
            }
            asm volatile("cp.async.commit_group;" ::: "memory");
            asm volatile("cp.async.wait_group 1;" ::: "memory");
        } else {
            asm volatile("cp.async.wait_group 0;" ::: "memory");
        }
        __syncthreads();

        const __half* Kb = Ks + buf * KVT_H;
        const __half* Vb = Vs + buf * KVT_H;

        // S = Q @ K^T  (16 x 64 strip): 8 n-groups x 4 k16 steps
        float s[8][4];
        #pragma unroll
        for (int nj = 0; nj < 8; ++nj) { s[nj][0]=0.f; s[nj][1]=0.f; s[nj][2]=0.f; s[nj][3]=0.f; }
        #pragma unroll
        for (int nj = 0; nj < 8; ++nj) {
            const __half* kr = Kb + (nj * 8 + lr) * KVPADH + 2 * lc;
            #pragma unroll
            for (int kk = 0; kk < 4; ++kk) {
                uint32_t bf[2];
                bf[0] = *(const uint32_t*)(kr + kk * 16);
                bf[1] = *(const uint32_t*)(kr + kk * 16 + 8);
                mma16816(s[nj], qa[kk], bf);
            }
        }

        // online softmax (rows lr and lr+8)
        float rmax0 = -1e30f, rmax1 = -1e30f;
        #pragma unroll
        for (int nj = 0; nj < 8; ++nj) {
            rmax0 = fmaxf(rmax0, fmaxf(s[nj][0], s[nj][1]));
            rmax1 = fmaxf(rmax1, fmaxf(s[nj][2], s[nj][3]));
        }
        rmax0 = fmaxf(rmax0, __shfl_xor_sync(0xffffffffu, rmax0, 1));
        rmax0 = fmaxf(rmax0, __shfl_xor_sync(0xffffffffu, rmax0, 2));
        rmax1 = fmaxf(rmax1, __shfl_xor_sync(0xffffffffu, rmax1, 1));
        rmax1 = fmaxf(rmax1, __shfl_xor_sync(0xffffffffu, rmax1, 2));
        float mn0 = fmaxf(m0, rmax0), mn1 = fmaxf(m1, rmax1);
        float corr0 = __expf(m0 - mn0), corr1 = __expf(m1 - mn1);
        m0 = mn0; m1 = mn1;

        float ls0 = 0.f, ls1 = 0.f;
        #pragma unroll
        for (int nj = 0; nj < 8; ++nj) {
            s[nj][0] = __expf(s[nj][0] - mn0);
            s[nj][1] = __expf(s[nj][1] - mn0);
            s[nj][2] = __expf(s[nj][2] - mn1);
            s[nj][3] = __expf(s[nj][3] - mn1);
            ls0 += s[nj][0] + s[nj][1];
            ls1 += s[nj][2] + s[nj][3];
        }
        ls0 += __shfl_xor_sync(0xffffffffu, ls0, 1);
        ls0 += __shfl_xor_sync(0xffffffffu, ls0, 2);
        ls1 += __shfl_xor_sync(0xffffffffu, ls1, 1);
        ls1 += __shfl_xor_sync(0xffffffffu, ls1, 2);
        l0 = l0 * corr0 + ls0;
        l1 = l1 * corr1 + ls1;

        #pragma unroll
        for (int nj = 0; nj < 8; ++nj) {
            o[nj][0] *= corr0; o[nj][1] *= corr0;
            o[nj][2] *= corr1; o[nj][3] *= corr1;
        }

        // O += P @ V : P re-frag is thread-local; V via ldmatrix.x4.trans
        const int vj = lane >> 3, vi = lane & 7;    // ldmatrix source-row lanes
        #pragma unroll
        for (int kk2 = 0; kk2 < 4; ++kk2) {
            uint32_t pa[4];
            pa[0] = packh2(s[2*kk2][0],   s[2*kk2][1]);
            pa[1] = packh2(s[2*kk2][2],   s[2*kk2][3]);
            pa[2] = packh2(s[2*kk2+1][0], s[2*kk2+1][1]);
            pa[3] = packh2(s[2*kk2+1][2], s[2*kk2+1][3]);
            #pragma unroll
            for (int dg = 0; dg < 4; ++dg) {
                uint32_t vb[4];
                uint32_t addr = smem_u32(Vb + (kk2 * 16 + (vj & 1) * 8 + vi) * KVPADH
                                            + dg * 16 + (vj >> 1) * 8);
                ldsm_x4_t(vb, addr);
                mma16816(o[dg * 2],     pa, &vb[0]);
                mma16816(o[dg * 2 + 1], pa, &vb[2]);
            }
        }
        __syncthreads();
    }

    float inv0 = 1.0f / l0, inv1 = 1.0f / l1;
    size_t row = (size_t)(b * NSEQ + qrow0 + lr);
    #pragma unroll
    for (int nj2 = 0; nj2 < 8; ++nj2) {
        int col = h * HDIM + nj2 * 8 + 2 * lc;
        __half2 h0 = __floats2half2_rn(o[nj2][0] * inv0, o[nj2][1] * inv0);
        __half2 h1 = __floats2half2_rn(o[nj2][2] * inv1, o[nj2][3] * inv1);
        *(__half2*)&o_out[row * CDIM + col]       = h0;
        *(__half2*)&o_out[(row + 8) * CDIM + col] = h1;
    }
}

// ---------------- host launch ----------------
extern "C" void kernel_launch(void* const* d_in, const int* in_sizes, int n_in,
                              void* d_out, int out_size) {
    const float* x      = (const float*)d_in[0];
    const float* ln1_g  = (const float*)d_in[1];
    const float* ln1_b  = (const float*)d_in[2];
    const float* w_qkv  = (const float*)d_in[3];
    const float* w_proj = (const float*)d_in[4];
    const float* b_proj = (const float*)d_in[5];
    const float* ln2_g  = (const float*)d_in[6];
    const float* ln2_b  = (const float*)d_in[7];
    const float* w_fc1  = (const float*)d_in[8];
    const float* b_fc1  = (const float*)d_in[9];
    const float* w_fc2  = (const float*)d_in[10];
    const float* b_fc2  = (const float*)d_in[11];
    float* out = (float*)d_out;

    __half *h, *o, *h2, *ff, *qkv, *wqkvT, *wprojT, *wfc1T, *wfc2T;
    float *x1;
    cudaGetSymbolAddress((void**)&h,      g_h);
    cudaGetSymbolAddress((void**)&qkv,    g_qkv);
    cudaGetSymbolAddress((void**)&o,      g_o);
    cudaGetSymbolAddress((void**)&x1,     g_x1);
    cudaGetSymbolAddress((void**)&h2,     g_h2);
    cudaGetSymbolAddress((void**)&ff,     g_ff);
    cudaGetSymbolAddress((void**)&wqkvT,  g_wqkvT);
    cudaGetSymbolAddress((void**)&wprojT, g_wprojT);
    cudaGetSymbolAddress((void**)&wfc1T,  g_wfc1T);
    cudaGetSymbolAddress((void**)&wfc2T,  g_wfc2T);

    cudaFuncSetAttribute(gemm_h<0>, cudaFuncAttributeMaxDynamicSharedMemorySize, GEMM_SMEM);
    cudaFuncSetAttribute(gemm_h<1>, cudaFuncAttributeMaxDynamicSharedMemorySize, GEMM_SMEM);
    cudaFuncSetAttribute(gemm_h<2>, cudaFuncAttributeMaxDynamicSharedMemorySize, GEMM_SMEM);
    cudaFuncSetAttribute(attn_mma,  cudaFuncAttributeMaxDynamicSharedMemorySize, AT_SMEM);

    dim3 tb(32, 8);
    transpose_k<<<dim3(3 * CDIM / 32, CDIM / 32), tb>>>(w_qkv, wqkvT, CDIM, 3 * CDIM);
    transpose_k<<<dim3(CDIM / 32, CDIM / 32), tb>>>(w_proj, wprojT, CDIM, CDIM);
    transpose_k<<<dim3(FFDIM / 32, CDIM / 32), tb>>>(w_fc1, wfc1T, CDIM, FFDIM);
    transpose_k<<<dim3(CDIM / 32, FFDIM / 32), tb>>>(w_fc2, wfc2T, FFDIM, CDIM);

    // 1. LN1 (fp16 out)
    ln_kernel<<<M_ROWS, 256>>>(x, ln1_g, ln1_b, h);
    // 2. qkv = h @ w_qkv (fp16 out)
    gemm_h<0><<<dim3(3 * CDIM / 128, M_ROWS / 128), 256, GEMM_SMEM>>>(
        h, wqkvT, nullptr, nullptr, qkv, 3 * CDIM, CDIM);
    // 3. attention (fp16 tensor core)
    attn_mma<<<dim3(NSEQ / 128, 2 * NHEAD), 256, AT_SMEM>>>(qkv, o);
    // 4. x1 = x + o @ w_proj + b_proj (fp32)
    gemm_h<1><<<dim3(CDIM / 128, M_ROWS / 128), 256, GEMM_SMEM>>>(
        o, wprojT, b_proj, x, x1, CDIM, CDIM);
    // 5. LN2 (fp16 out)
    ln_kernel<<<M_ROWS, 256>>>(x1, ln2_g, ln2_b, h2);
    // 6. ff = fp16(gelu(h2 @ w_fc1 + b_fc1))
    gemm_h<2><<<dim3(FFDIM / 128, M_ROWS / 128), 256, GEMM_SMEM>>>(
        h2, wfc1T, b_fc1, nullptr, ff, FFDIM, CDIM);
    // 7. out = x1 + ff @ w_fc2 + b_fc2 (fp32)
    gemm_h<1><<<dim3(CDIM / 128, M_ROWS / 128), 256, GEMM_SMEM>>>(
        ff, wfc2T, b_fc2, x1, out, CDIM, FFDIM);
}